// round 14
// baseline (speedup 1.0000x reference)
#include <cuda_runtime.h>
#include <cuda_bf16.h>
#include <cstdint>
#include <cstddef>

// ---------------------------------------------------------------------------
// BidirectionalMambaBlock — HMMA bf16 GEMMs (double-buffered 1-pass big /
// 2-pass xproj splitK8) + chunked scan; dtproj fuses split-K reduce
// ---------------------------------------------------------------------------

#define L_SEQ   1024
#define BATCH   2
#define DMODEL  512
#define DINNER  1024
#define DSTATE  16
#define DTRANK  32
#define MROWS   (BATCH * L_SEQ)     // 2048
#define CH      8
#define TC      (L_SEQ / CH)        // 128
#define XKS     8                   // split-K for xproj (HMMA)

#define WI_SZ   (2 * DINNER * DMODEL)
#define WO_SZ   (DMODEL * DINNER)
#define FW_SZ   (DMODEL * 2 * DMODEL)
#define XPW_SZ  (64 * DINNER)

// ------------------------- scratch (device globals) ------------------------
__device__ float g_xdbl[(size_t)2 * MROWS * 64];
__device__ float g_xpart[(size_t)2 * XKS * MROWS * 64];
__device__ float g_delta[(size_t)2 * MROWS * DINNER];
__device__ float g_r[(size_t)MROWS * DMODEL];
__device__ float g_Aval[2 * DINNER * DSTATE];
__device__ float g_hpart[(size_t)4 * CH * DINNER * DSTATE];
__device__ float g_hin[(size_t)4 * CH * DINNER * DSTATE];
__device__ float g_sumd[(size_t)4 * CH * DINNER];

// bf16 operands / intermediates (16B-aligned)
__device__ __align__(128) __nv_bfloat16 g_xz[(size_t)2 * MROWS * 2 * DINNER];
__device__ __align__(128) __nv_bfloat16 g_xhi[(size_t)MROWS * DMODEL];
__device__ __align__(128) __nv_bfloat16 g_wihi[(size_t)2 * WI_SZ];
__device__ __align__(128) __nv_bfloat16 g_wohi[(size_t)2 * WO_SZ];
__device__ __align__(128) __nv_bfloat16 g_fwhi[(size_t)FW_SZ];
__device__ __align__(128) __nv_bfloat16 g_xpwhi[(size_t)2 * XPW_SZ];
__device__ __align__(128) __nv_bfloat16 g_xpwlo[(size_t)2 * XPW_SZ];
__device__ __align__(128) __nv_bfloat16 g_xihi[(size_t)2 * MROWS * DINNER];
__device__ __align__(128) __nv_bfloat16 g_yhi[(size_t)2 * MROWS * DINNER];
__device__ __align__(128) __nv_bfloat16 g_fuhi[(size_t)MROWS * 2 * DMODEL];

// ------------------------------ device helpers -----------------------------
__device__ __forceinline__ float2 ffma2(float2 a, float2 b, float2 c) {
    unsigned long long ua = *reinterpret_cast<unsigned long long*>(&a);
    unsigned long long ub = *reinterpret_cast<unsigned long long*>(&b);
    unsigned long long uc = *reinterpret_cast<unsigned long long*>(&c);
    unsigned long long ud;
    asm("fma.rn.f32x2 %0, %1, %2, %3;" : "=l"(ud) : "l"(ua), "l"(ub), "l"(uc));
    return *reinterpret_cast<float2*>(&ud);
}
__device__ __forceinline__ float ex2f(float x) {
    float y; asm("ex2.approx.ftz.f32 %0, %1;" : "=f"(y) : "f"(x)); return y;
}
__device__ __forceinline__ float softplusf(float x) {
    return (x > 15.0f) ? x : __logf(1.0f + __expf(x));
}
__device__ __forceinline__ float siluf(float x) {
    return __fdividef(x, 1.0f + __expf(-x));
}
__device__ __forceinline__ uint32_t smem_u32(const void* p) {
    uint32_t a;
    asm("{ .reg .u64 t; cvta.to.shared.u64 t, %1; cvt.u32.u64 %0, t; }" : "=r"(a) : "l"(p));
    return a;
}
__device__ __forceinline__ void ldsm4(uint32_t* r, uint32_t addr) {
    asm volatile("ldmatrix.sync.aligned.m8n8.x4.shared.b16 {%0,%1,%2,%3}, [%4];"
                 : "=r"(r[0]), "=r"(r[1]), "=r"(r[2]), "=r"(r[3]) : "r"(addr));
}
__device__ __forceinline__ void mma_bf16(float* c, const uint32_t* a, const uint32_t* b) {
    asm volatile(
        "mma.sync.aligned.m16n8k16.row.col.f32.bf16.bf16.f32 "
        "{%0,%1,%2,%3}, {%4,%5,%6,%7}, {%8,%9}, {%0,%1,%2,%3};"
        : "+f"(c[0]), "+f"(c[1]), "+f"(c[2]), "+f"(c[3])
        : "r"(a[0]), "r"(a[1]), "r"(a[2]), "r"(a[3]), "r"(b[0]), "r"(b[1]));
}
__device__ __forceinline__ unsigned short bits(__nv_bfloat16 v) {
    return *reinterpret_cast<unsigned short*>(&v);
}
__device__ __forceinline__ float bf2f(__nv_bfloat16 v) { return __bfloat162float(v); }
__device__ __forceinline__ float4 ld4bf(const __nv_bfloat16* p) {
    ushort4 u = *reinterpret_cast<const ushort4*>(p);
    float4 f;
    f.x = bf2f(*reinterpret_cast<__nv_bfloat16*>(&u.x));
    f.y = bf2f(*reinterpret_cast<__nv_bfloat16*>(&u.y));
    f.z = bf2f(*reinterpret_cast<__nv_bfloat16*>(&u.z));
    f.w = bf2f(*reinterpret_cast<__nv_bfloat16*>(&u.w));
    return f;
}

// ------------- fused prep: bf16 hi(/lo) conversions + A' segments -----------
struct PrepJobs {
    const float4* src[10];
    ushort4* hi[10];
    ushort4* lo[10];   // nullptr -> no lo plane
    float4* fo[10];    // non-null -> A' mode: out = -exp(v)*log2e (fp32)
    int end4[10];
};

__global__ void prep_all_kernel(PrepJobs J)
{
    const int i = blockIdx.x * 256 + threadIdx.x;
    if (i >= J.end4[9]) return;
    int s = 0;
#pragma unroll
    for (int k = 0; k < 9; k++) s += (i >= J.end4[k]) ? 1 : 0;
    const int base = s ? J.end4[s - 1] : 0;
    const int off = i - base;

    const float4 v = J.src[s][off];
    if (J.fo[s]) {
        float4 o;
        o.x = -__expf(v.x) * 1.4426950408889634f;
        o.y = -__expf(v.y) * 1.4426950408889634f;
        o.z = -__expf(v.z) * 1.4426950408889634f;
        o.w = -__expf(v.w) * 1.4426950408889634f;
        J.fo[s][off] = o;
        return;
    }
    __nv_bfloat16 h0 = __float2bfloat16(v.x), h1 = __float2bfloat16(v.y);
    __nv_bfloat16 h2 = __float2bfloat16(v.z), h3 = __float2bfloat16(v.w);
    ushort4 uh; uh.x = bits(h0); uh.y = bits(h1); uh.z = bits(h2); uh.w = bits(h3);
    J.hi[s][off] = uh;
    if (J.lo[s]) {
        ushort4 ul;
        ul.x = bits(__float2bfloat16(v.x - bf2f(h0)));
        ul.y = bits(__float2bfloat16(v.y - bf2f(h1)));
        ul.z = bits(__float2bfloat16(v.z - bf2f(h2)));
        ul.w = bits(__float2bfloat16(v.w - bf2f(h3)));
        J.lo[s][off] = ul;
    }
}

// -------------------- HMMA bf16 GEMM (NT), dir-batched ----------------------
// FAST (!BSPLIT): 1-pass, double-buffered smem, 1 sync/chunk.
// BSPLIT: 2-pass B hi/lo (A hi only), single-buffered (xproj).
// CTA tile 128x64, BK=32, 4 warps. blockIdx.z = dir*KS + ks.
// OUTMODE 0: fp32 C; 1: bf16 hi C.
template<bool FLIPA, bool FLIPSTORE, int OUTMODE, bool BSPLIT, int KS>
__global__ void __launch_bounds__(128)
mma_gemm(const __nv_bfloat16* __restrict__ Ahi,
         const __nv_bfloat16* __restrict__ Bhi0, const __nv_bfloat16* __restrict__ Blo0,
         const __nv_bfloat16* __restrict__ Bhi1, const __nv_bfloat16* __restrict__ Blo1,
         float* __restrict__ Cf, __nv_bfloat16* __restrict__ Chi,
         size_t aStride, size_t cStride, size_t sliceStride,
         int K, int lda, int ldb, int ldc)
{
    __shared__ __align__(16) __nv_bfloat16 sA[2][128][40];
    __shared__ __align__(16) __nv_bfloat16 sB[2][64][40];

    const int tid = threadIdx.x;
    const int warp = tid >> 5, lane = tid & 31;
    const int wm = warp >> 1, wn = warp & 1;
    const int z = blockIdx.z;
    const int dir = z / KS, ks = z % KS;
    const int bm = blockIdx.y * 128, bn = blockIdx.x * 64;

    const __nv_bfloat16* __restrict__ Bh = dir ? Bhi1 : Bhi0;
    const __nv_bfloat16* __restrict__ Bl = dir ? Blo1 : Blo0;
    Ahi += (size_t)dir * aStride;

    const int kBase = ks * (K / KS);
    const int nCh = (K / KS) >> 5;

    float acc[4][4][4];
#pragma unroll
    for (int i = 0; i < 4; i++)
#pragma unroll
        for (int j = 0; j < 4; j++)
#pragma unroll
            for (int e = 0; e < 4; e++) acc[i][j][e] = 0.0f;

    const int arow = wm * 64 + (lane & 15);
    const int acol = (lane >> 4) << 3;
    const int brow = wn * 32 + ((lane >> 4) << 3) + (lane & 7);
    const int bcol = ((lane >> 3) & 1) << 3;

    const uint32_t sa0 = smem_u32(&sA[0][0][0]);
    const uint32_t sa1 = smem_u32(&sA[1][0][0]);
    const uint32_t sb0 = smem_u32(&sB[0][0][0]);
    const uint32_t sb1 = smem_u32(&sB[1][0][0]);

    if (!BSPLIT) {
        uint4 ra[4], rb[2];
#pragma unroll
        for (int i = 0; i < 4; i++) {
            const int idx = i * 128 + tid, row = idx >> 2, q = idx & 3;
            int gr = bm + row; if (FLIPA && dir) gr ^= (L_SEQ - 1);
            ra[i] = *reinterpret_cast<const uint4*>(Ahi + (size_t)gr * lda + kBase + q * 8);
        }
#pragma unroll
        for (int i = 0; i < 2; i++) {
            const int idx = i * 128 + tid, row = idx >> 2, q = idx & 3;
            rb[i] = *reinterpret_cast<const uint4*>(Bh + (size_t)(bn + row) * ldb + kBase + q * 8);
        }
#pragma unroll
        for (int i = 0; i < 4; i++) {
            const int idx = i * 128 + tid, row = idx >> 2, q = idx & 3;
            *reinterpret_cast<uint4*>(&sA[0][row][q * 8]) = ra[i];
        }
#pragma unroll
        for (int i = 0; i < 2; i++) {
            const int idx = i * 128 + tid, row = idx >> 2, q = idx & 3;
            *reinterpret_cast<uint4*>(&sB[0][row][q * 8]) = rb[i];
        }
        if (nCh > 1) {
            const int k0 = kBase + 32;
#pragma unroll
            for (int i = 0; i < 4; i++) {
                const int idx = i * 128 + tid, row = idx >> 2, q = idx & 3;
                int gr = bm + row; if (FLIPA && dir) gr ^= (L_SEQ - 1);
                ra[i] = *reinterpret_cast<const uint4*>(Ahi + (size_t)gr * lda + k0 + q * 8);
            }
#pragma unroll
            for (int i = 0; i < 2; i++) {
                const int idx = i * 128 + tid, row = idx >> 2, q = idx & 3;
                rb[i] = *reinterpret_cast<const uint4*>(Bh + (size_t)(bn + row) * ldb + k0 + q * 8);
            }
        }
        __syncthreads();

        for (int ch = 0; ch < nCh; ++ch) {
            const int cur = ch & 1, nxt = cur ^ 1;
            if (ch + 1 < nCh) {
#pragma unroll
                for (int i = 0; i < 4; i++) {
                    const int idx = i * 128 + tid, row = idx >> 2, q = idx & 3;
                    *reinterpret_cast<uint4*>(&sA[nxt][row][q * 8]) = ra[i];
                }
#pragma unroll
                for (int i = 0; i < 2; i++) {
                    const int idx = i * 128 + tid, row = idx >> 2, q = idx & 3;
                    *reinterpret_cast<uint4*>(&sB[nxt][row][q * 8]) = rb[i];
                }
                if (ch + 2 < nCh) {
                    const int k0 = kBase + ((ch + 2) << 5);
#pragma unroll
                    for (int i = 0; i < 4; i++) {
                        const int idx = i * 128 + tid, row = idx >> 2, q = idx & 3;
                        int gr = bm + row; if (FLIPA && dir) gr ^= (L_SEQ - 1);
                        ra[i] = *reinterpret_cast<const uint4*>(Ahi + (size_t)gr * lda + k0 + q * 8);
                    }
#pragma unroll
                    for (int i = 0; i < 2; i++) {
                        const int idx = i * 128 + tid, row = idx >> 2, q = idx & 3;
                        rb[i] = *reinterpret_cast<const uint4*>(Bh + (size_t)(bn + row) * ldb + k0 + q * 8);
                    }
                }
            }
            const uint32_t sa = cur ? sa1 : sa0;
            const uint32_t sb = cur ? sb1 : sb0;
#pragma unroll
            for (int k16 = 0; k16 < 32; k16 += 16) {
                uint32_t ah[4][4], bh[2][4];
#pragma unroll
                for (int mi = 0; mi < 4; mi++)
                    ldsm4(ah[mi], sa + ((uint32_t)(arow + mi * 16) * 40 + k16 + acol) * 2);
#pragma unroll
                for (int p = 0; p < 2; p++)
                    ldsm4(bh[p], sb + ((uint32_t)(brow + p * 16) * 40 + k16 + bcol) * 2);
#pragma unroll
                for (int mi = 0; mi < 4; mi++)
#pragma unroll
                    for (int nj = 0; nj < 4; nj++)
                        mma_bf16(acc[mi][nj], ah[mi], &bh[nj >> 1][(nj & 1) * 2]);
            }
            __syncthreads();
        }
    } else {
        uint4 ra[4], rb[2][2];
#pragma unroll
        for (int i = 0; i < 4; i++) {
            const int idx = i * 128 + tid, row = idx >> 2, q = idx & 3;
            int gr = bm + row; if (FLIPA && dir) gr ^= (L_SEQ - 1);
            ra[i] = *reinterpret_cast<const uint4*>(Ahi + (size_t)gr * lda + kBase + q * 8);
        }
#pragma unroll
        for (int i = 0; i < 2; i++) {
            const int idx = i * 128 + tid, row = idx >> 2, q = idx & 3;
            const size_t off = (size_t)(bn + row) * ldb + kBase + q * 8;
            rb[0][i] = *reinterpret_cast<const uint4*>(Bh + off);
            rb[1][i] = *reinterpret_cast<const uint4*>(Bl + off);
        }

        for (int ch = 0; ch < nCh; ++ch) {
#pragma unroll
            for (int i = 0; i < 4; i++) {
                const int idx = i * 128 + tid, row = idx >> 2, q = idx & 3;
                *reinterpret_cast<uint4*>(&sA[0][row][q * 8]) = ra[i];
            }
#pragma unroll
            for (int i = 0; i < 2; i++) {
                const int idx = i * 128 + tid, row = idx >> 2, q = idx & 3;
                *reinterpret_cast<uint4*>(&sB[0][row][q * 8]) = rb[0][i];
                *reinterpret_cast<uint4*>(&sB[1][row][q * 8]) = rb[1][i];
            }
            __syncthreads();

            if (ch + 1 < nCh) {
                const int k0 = kBase + ((ch + 1) << 5);
#pragma unroll
                for (int i = 0; i < 4; i++) {
                    const int idx = i * 128 + tid, row = idx >> 2, q = idx & 3;
                    int gr = bm + row; if (FLIPA && dir) gr ^= (L_SEQ - 1);
                    ra[i] = *reinterpret_cast<const uint4*>(Ahi + (size_t)gr * lda + k0 + q * 8);
                }
#pragma unroll
                for (int i = 0; i < 2; i++) {
                    const int idx = i * 128 + tid, row = idx >> 2, q = idx & 3;
                    const size_t off = (size_t)(bn + row) * ldb + k0 + q * 8;
                    rb[0][i] = *reinterpret_cast<const uint4*>(Bh + off);
                    rb[1][i] = *reinterpret_cast<const uint4*>(Bl + off);
                }
            }

#pragma unroll
            for (int k16 = 0; k16 < 32; k16 += 16) {
                uint32_t ah[4][4], bh[2][4], bl[2][4];
#pragma unroll
                for (int mi = 0; mi < 4; mi++)
                    ldsm4(ah[mi], sa0 + ((uint32_t)(arow + mi * 16) * 40 + k16 + acol) * 2);
#pragma unroll
                for (int p = 0; p < 2; p++) {
                    const uint32_t off = ((uint32_t)(brow + p * 16) * 40 + k16 + bcol) * 2;
                    ldsm4(bh[p], sb0 + off);
                    ldsm4(bl[p], sb1 + off);
                }
#pragma unroll
                for (int mi = 0; mi < 4; mi++)
#pragma unroll
                    for (int nj = 0; nj < 4; nj++) {
                        mma_bf16(acc[mi][nj], ah[mi], &bh[nj >> 1][(nj & 1) * 2]);
                        mma_bf16(acc[mi][nj], ah[mi], &bl[nj >> 1][(nj & 1) * 2]);
                    }
            }
            __syncthreads();
        }
    }

    // epilogue
    if (OUTMODE == 0) Cf += (size_t)dir * cStride + (size_t)ks * sliceStride;
    else Chi += (size_t)dir * cStride;

#pragma unroll
    for (int mi = 0; mi < 4; mi++) {
#pragma unroll
        for (int nj = 0; nj < 4; nj++) {
            const int col = bn + wn * 32 + nj * 8 + (lane & 3) * 2;
            int r0 = bm + wm * 64 + mi * 16 + (lane >> 2);
            int r1 = r0 + 8;
            if (FLIPSTORE && dir) { r0 ^= (L_SEQ - 1); r1 ^= (L_SEQ - 1); }
            const float* a = acc[mi][nj];
            if (OUTMODE == 0) {
                *reinterpret_cast<float2*>(Cf + (size_t)r0 * ldc + col) = make_float2(a[0], a[1]);
                *reinterpret_cast<float2*>(Cf + (size_t)r1 * ldc + col) = make_float2(a[2], a[3]);
            } else {
                ushort2 u0, u1;
                u0.x = bits(__float2bfloat16(a[0]));
                u0.y = bits(__float2bfloat16(a[1]));
                u1.x = bits(__float2bfloat16(a[2]));
                u1.y = bits(__float2bfloat16(a[3]));
                *reinterpret_cast<ushort2*>(Chi + (size_t)r0 * ldc + col) = u0;
                *reinterpret_cast<ushort2*>(Chi + (size_t)r1 * ldc + col) = u1;
            }
        }
    }
}

// ---------------- pipelined SIMT SGEMM (NT) — dtproj only -------------------
// SUMKS > 1: A loads sum SUMKS slices (stride sliceA) — fuses split-K reduce.
template<int BM, int BN, int BK, int TM, int TN, bool SOFTPLUS, int SUMKS>
__global__ void __launch_bounds__((BM / TM) * (BN / TN))
gemm_nt(const float* __restrict__ A, const float* __restrict__ B0,
        const float* __restrict__ B1, float* __restrict__ C,
        const float* __restrict__ bias0, const float* __restrict__ bias1,
        size_t aStride, size_t cStride, size_t sliceA,
        int M, int N, int K, int lda, int ldb, int ldc)
{
    constexpr int NTHR = (BM / TM) * (BN / TN);
    constexpr int TX = BN / TN;
    constexpr int PAD = 4;
    constexpr int AKT = BK / 4;
    constexpr int ALD = (BM * BK) / (NTHR * 4);
    constexpr int BLD = (BN * BK) / (NTHR * 4);
    constexpr int ARS = NTHR / AKT;

    __shared__ __align__(16) float As[2][BK][BM + PAD];
    __shared__ __align__(16) float Bs[2][BK][BN + PAD];

    const int dir = blockIdx.z;
    const float* __restrict__ Bw = dir ? B1 : B0;
    const float* __restrict__ bias = dir ? bias1 : bias0;
    A += (size_t)dir * aStride;
    C += (size_t)dir * cStride;

    const int tid = threadIdx.x;
    const int bn = blockIdx.x * BN;
    const int bm = blockIdx.y * BM;
    const int tx = tid % TX;
    const int ty = tid / TX;
    const int ar = tid / AKT;
    const int ac = (tid % AKT) * 4;

    const int nIter = K / BK;

    float2 acc[TM][TN / 2];
#pragma unroll
    for (int i = 0; i < TM; i++)
#pragma unroll
        for (int j = 0; j < TN / 2; j++) acc[i][j] = make_float2(0.0f, 0.0f);

    float4 ra[ALD], rb[BLD];

    auto loadA = [&](int kg, int i) -> float4 {
        const size_t base = (size_t)(bm + ar + i * ARS) * lda + kg + ac;
        float4 v = *reinterpret_cast<const float4*>(A + base);
        if (SUMKS > 1) {
#pragma unroll
            for (int s = 1; s < SUMKS; s++) {
                float4 w = *reinterpret_cast<const float4*>(A + base + (size_t)s * sliceA);
                v.x += w.x; v.y += w.y; v.z += w.z; v.w += w.w;
            }
        }
        return v;
    };

#pragma unroll
    for (int i = 0; i < ALD; i++) ra[i] = loadA(0, i);
#pragma unroll
    for (int i = 0; i < BLD; i++)
        rb[i] = *reinterpret_cast<const float4*>(Bw + (size_t)(bn + ar + i * ARS) * ldb + ac);

#pragma unroll
    for (int i = 0; i < ALD; i++) {
        int r = ar + i * ARS;
        As[0][ac + 0][r] = ra[i].x; As[0][ac + 1][r] = ra[i].y;
        As[0][ac + 2][r] = ra[i].z; As[0][ac + 3][r] = ra[i].w;
    }
#pragma unroll
    for (int i = 0; i < BLD; i++) {
        int r = ar + i * ARS;
        Bs[0][ac + 0][r] = rb[i].x; Bs[0][ac + 1][r] = rb[i].y;
        Bs[0][ac + 2][r] = rb[i].z; Bs[0][ac + 3][r] = rb[i].w;
    }
    __syncthreads();

    for (int it = 0; it < nIter; ++it) {
        const int cur = it & 1;
        const bool more = (it + 1 < nIter);
        if (more) {
            const int kg = (it + 1) * BK;
#pragma unroll
            for (int i = 0; i < ALD; i++) ra[i] = loadA(kg, i);
#pragma unroll
            for (int i = 0; i < BLD; i++)
                rb[i] = *reinterpret_cast<const float4*>(Bw + (size_t)(bn + ar + i * ARS) * ldb + kg + ac);
        }

#pragma unroll
        for (int k = 0; k < BK; k++) {
            float a[TM];
            float2 b2[TN / 2];
#pragma unroll
            for (int i = 0; i < TM; i += 4) {
                float4 t = *reinterpret_cast<const float4*>(&As[cur][k][ty * TM + i]);
                a[i] = t.x; a[i + 1] = t.y; a[i + 2] = t.z; a[i + 3] = t.w;
            }
#pragma unroll
            for (int j = 0; j < TN; j += 4) {
                float4 t = *reinterpret_cast<const float4*>(&Bs[cur][k][tx * TN + j]);
                b2[j / 2]     = make_float2(t.x, t.y);
                b2[j / 2 + 1] = make_float2(t.z, t.w);
            }
#pragma unroll
            for (int i = 0; i < TM; i++) {
                float2 a2 = make_float2(a[i], a[i]);
#pragma unroll
                for (int j = 0; j < TN / 2; j++)
                    acc[i][j] = ffma2(a2, b2[j], acc[i][j]);
            }
        }

        if (more) {
            const int nxt = cur ^ 1;
#pragma unroll
            for (int i = 0; i < ALD; i++) {
                int r = ar + i * ARS;
                As[nxt][ac + 0][r] = ra[i].x; As[nxt][ac + 1][r] = ra[i].y;
                As[nxt][ac + 2][r] = ra[i].z; As[nxt][ac + 3][r] = ra[i].w;
            }
#pragma unroll
            for (int i = 0; i < BLD; i++) {
                int r = ar + i * ARS;
                Bs[nxt][ac + 0][r] = rb[i].x; Bs[nxt][ac + 1][r] = rb[i].y;
                Bs[nxt][ac + 2][r] = rb[i].z; Bs[nxt][ac + 3][r] = rb[i].w;
            }
            __syncthreads();
        }
    }

#pragma unroll
    for (int i = 0; i < TM; i++) {
        int m = bm + ty * TM + i;
#pragma unroll
        for (int j = 0; j < TN / 2; j++) {
            int n = bn + tx * TN + 2 * j;
            float2 v = acc[i][j];
            if (SOFTPLUS) {
                v.x = softplusf(v.x + bias[n]);
                v.y = softplusf(v.y + bias[n + 1]);
            }
            *reinterpret_cast<float2*>(C + (size_t)m * ldc + n) = v;
        }
    }
}

// ----------------- split-K reduce for xproj B/C columns (32..63) ------------
__global__ void xdbl_reduce_kernel()
{
    const int idx = blockIdx.x * 256 + threadIdx.x;   // 2*2048*32 elems
    const int half = MROWS * 32;
    const int dir = idx / half;
    const int off = idx - dir * half;
    const int m = off >> 5, c = (off & 31) + 32;
    const size_t per = (size_t)MROWS * 64;
    const size_t e = (size_t)m * 64 + c;
    float s = 0.0f;
#pragma unroll
    for (int ks = 0; ks < XKS; ks++)
        s += g_xpart[((size_t)dir * XKS + ks) * per + e];
    g_xdbl[(size_t)dir * per + e] = s;
}

// -------- causal depthwise conv + SiLU (rolling 8-step) -> bf16 hi ----------
__global__ void conv_silu_kernel(const float* __restrict__ cwf, const float* __restrict__ cbf,
                                 const float* __restrict__ cwb, const float* __restrict__ cbb)
{
    const int tb   = blockIdx.x;
    const int dirb = blockIdx.y;
    const int dir = dirb >> 1, b = dirb & 1;
    const int l0 = tb * 8;
    const int d0 = threadIdx.x * 4;
    const float* cw = dir ? cwb : cwf;
    const float* cb = dir ? cbb : cbf;

    float4 w0 = *reinterpret_cast<const float4*>(cw + (size_t)(d0 + 0) * 4);
    float4 w1 = *reinterpret_cast<const float4*>(cw + (size_t)(d0 + 1) * 4);
    float4 w2 = *reinterpret_cast<const float4*>(cw + (size_t)(d0 + 2) * 4);
    float4 w3 = *reinterpret_cast<const float4*>(cw + (size_t)(d0 + 3) * 4);
    const float4 bias = *reinterpret_cast<const float4*>(cb + d0);

    const size_t base = ((size_t)dir * MROWS + (size_t)b * L_SEQ) * (2 * DINNER) + d0;
    const float4 zero = make_float4(0.f, 0.f, 0.f, 0.f);

    float4 xm3 = (l0 - 3 >= 0) ? ld4bf(g_xz + base + (size_t)(l0 - 3) * (2 * DINNER)) : zero;
    float4 xm2 = (l0 - 2 >= 0) ? ld4bf(g_xz + base + (size_t)(l0 - 2) * (2 * DINNER)) : zero;
    float4 xm1 = (l0 - 1 >= 0) ? ld4bf(g_xz + base + (size_t)(l0 - 1) * (2 * DINNER)) : zero;

    const size_t obase = ((size_t)dir * MROWS + (size_t)b * L_SEQ + l0) * DINNER + d0;

#pragma unroll
    for (int i = 0; i < 8; i++) {
        float4 xc = ld4bf(g_xz + base + (size_t)(l0 + i) * (2 * DINNER));
        float4 acc = bias;
        acc.x = fmaf(w0.x, xm3.x, fmaf(w0.y, xm2.x, fmaf(w0.z, xm1.x, fmaf(w0.w, xc.x, acc.x))));
        acc.y = fmaf(w1.x, xm3.y, fmaf(w1.y, xm2.y, fmaf(w1.z, xm1.y, fmaf(w1.w, xc.y, acc.y))));
        acc.z = fmaf(w2.x, xm3.z, fmaf(w2.y, xm2.z, fmaf(w2.z, xm1.z, fmaf(w2.w, xc.z, acc.z))));
        acc.w = fmaf(w3.x, xm3.w, fmaf(w3.y, xm2.w, fmaf(w3.z, xm1.w, fmaf(w3.w, xc.w, acc.w))));
        float4 o;
        o.x = siluf(acc.x); o.y = siluf(acc.y);
        o.z = siluf(acc.z); o.w = siluf(acc.w);

        ushort4 uh;
        uh.x = bits(__float2bfloat16(o.x));
        uh.y = bits(__float2bfloat16(o.y));
        uh.z = bits(__float2bfloat16(o.z));
        uh.w = bits(__float2bfloat16(o.w));
        *reinterpret_cast<ushort4*>(g_xihi + obase + (size_t)i * DINNER) = uh;

        xm3 = xm2; xm2 = xm1; xm1 = xc;
    }
}

// ------------------------------ chunked selective scan ----------------------
__global__ void scanA_kernel()
{
    const int db  = blockIdx.z;
    const int dir = db >> 1, b = db & 1;
    const int c   = blockIdx.y;
    const int t   = threadIdx.x;
    const int g4  = t & 3;
    const int d   = blockIdx.x * 32 + (t >> 2);

    const size_t rb = ((size_t)dir * MROWS + (size_t)b * L_SEQ + (size_t)c * TC) * DINNER + d;
    const float* __restrict__ dp = g_delta + rb;
    const __nv_bfloat16* __restrict__ xp = g_xihi + rb;
    const size_t xb = ((size_t)dir * MROWS + (size_t)b * L_SEQ + (size_t)c * TC) * 64;
    const float4* __restrict__ Bp = reinterpret_cast<const float4*>(g_xdbl + xb + 32) + g4;

    const float* ap = g_Aval + ((size_t)dir * DINNER + d) * DSTATE + 4 * g4;
    const float a0 = ap[0], a1 = ap[1], a2 = ap[2], a3 = ap[3];

    float h0 = 0.f, h1 = 0.f, h2 = 0.f, h3 = 0.f, sd = 0.f;

    for (int l = 0; l < TC; l++) {
        const float dlt = dp[(size_t)l * DINNER];
        const float xiv = bf2f(xp[(size_t)l * DINNER]);
        const float4 Bv = Bp[l * 16];
        const float u = dlt * xiv;
        h0 = fmaf(ex2f(dlt * a0), h0, u * Bv.x);
        h1 = fmaf(ex2f(dlt * a1), h1, u * Bv.y);
        h2 = fmaf(ex2f(dlt * a2), h2, u * Bv.z);
        h3 = fmaf(ex2f(dlt * a3), h3, u * Bv.w);
        sd += dlt;
    }
    const size_t hi = (((size_t)db * CH + c) * DINNER + d) * DSTATE + 4 * g4;
    float4 hv; hv.x = h0; hv.y = h1; hv.z = h2; hv.w = h3;
    *reinterpret_cast<float4*>(g_hpart + hi) = hv;
    if (g4 == 0) g_sumd[((size_t)db * CH + c) * DINNER + d] = sd;
}

__global__ void scanB_kernel()
{
    const int idx = blockIdx.x * 128 + threadIdx.x;
    const int g4 = idx & 3;
    const int d  = (idx >> 2) & (DINNER - 1);
    const int db = idx >> 12;
    const int dir = db >> 1;

    const float* ap = g_Aval + ((size_t)dir * DINNER + d) * DSTATE + 4 * g4;
    const float a0 = ap[0], a1 = ap[1], a2 = ap[2], a3 = ap[3];

    float h0 = 0.f, h1 = 0.f, h2 = 0.f, h3 = 0.f;
#pragma unroll
    for (int c = 0; c < CH; c++) {
        const size_t hi = (((size_t)db * CH + c) * DINNER + d) * DSTATE + 4 * g4;
        float4 hv; hv.x = h0; hv.y = h1; hv.z = h2; hv.w = h3;
        *reinterpret_cast<float4*>(g_hin + hi) = hv;
        const float S = g_sumd[((size_t)db * CH + c) * DINNER + d];
        const float4 hp = *reinterpret_cast<const float4*>(g_hpart + hi);
        h0 = fmaf(ex2f(S * a0), h0, hp.x);
        h1 = fmaf(ex2f(S * a1), h1, hp.y);
        h2 = fmaf(ex2f(S * a2), h2, hp.z);
        h3 = fmaf(ex2f(S * a3), h3, hp.w);
    }
}

__global__ void scanC_kernel(const float* __restrict__ Df, const float* __restrict__ Db)
{
    const int db  = blockIdx.z;
    const int dir = db >> 1, b = db & 1;
    const int c   = blockIdx.y;
    const int t   = threadIdx.x;
    const int g4  = t & 3;
    const int d   = blockIdx.x * 32 + (t >> 2);

    const size_t rb = ((size_t)dir * MROWS + (size_t)b * L_SEQ + (size_t)c * TC) * DINNER + d;
    const float* __restrict__ dp = g_delta + rb;
    const __nv_bfloat16* __restrict__ xp = g_xihi + rb;
    const size_t xb = ((size_t)dir * MROWS + (size_t)b * L_SEQ + (size_t)c * TC) * 64;
    const float4* __restrict__ Bp = reinterpret_cast<const float4*>(g_xdbl + xb + 32) + g4;
    const float4* __restrict__ Cp = reinterpret_cast<const float4*>(g_xdbl + xb + 48) + g4;
    const __nv_bfloat16* __restrict__ zp =
        g_xz + ((size_t)dir * MROWS + (size_t)b * L_SEQ + (size_t)c * TC) * (2 * DINNER) + DINNER + d;

    const float* ap = g_Aval + ((size_t)dir * DINNER + d) * DSTATE + 4 * g4;
    const float a0 = ap[0], a1 = ap[1], a2 = ap[2], a3 = ap[3];
    const float Dv = (dir ? Db : Df)[d];

    const size_t hi = (((size_t)db * CH + c) * DINNER + d) * DSTATE + 4 * g4;
    const float4 hin = *reinterpret_cast<const float4*>(g_hin + hi);
    float h0 = hin.x, h1 = hin.y, h2 = hin.z, h3 = hin.w;

    for (int l = 0; l < TC; l++) {
        const float dlt = dp[(size_t)l * DINNER];
        const float xiv = bf2f(xp[(size_t)l * DINNER]);
        const float4 Bv = Bp[l * 16];
        const float4 Cv = Cp[l * 16];
        const float u = dlt * xiv;
        h0 = fmaf(ex2f(dlt * a0), h0, u * Bv.x);
        h1 = fmaf(ex2f(dlt * a1), h1, u * Bv.y);
        h2 = fmaf(ex2f(dlt * a2), h2, u * Bv.z);
        h3 = fmaf(ex2f(dlt * a3), h3, u * Bv.w);
        float y = fmaf(h0, Cv.x, h1 * Cv.y) + fmaf(h2, Cv.z, h3 * Cv.w);
        y += __shfl_xor_sync(0xffffffffu, y, 1);
        y += __shfl_xor_sync(0xffffffffu, y, 2);
        if (g4 == 0) {
            const float z = bf2f(zp[(size_t)l * 2 * DINNER]);
            const float yv = fmaf(xiv, Dv, y) * siluf(z);
            g_yhi[rb + (size_t)l * DINNER] = __float2bfloat16(yv);
        }
    }
}

// ---------------- residual + fusion bias + LayerNorm ------------------------
__global__ void ln_kernel(const float* __restrict__ x, const float* __restrict__ fb,
                          const float* __restrict__ lg, const float* __restrict__ lb,
                          float* __restrict__ out)
{
    const int m = blockIdx.x;
    const int t = threadIdx.x;
    const float* rr = g_r + (size_t)m * DMODEL;
    const float* xr = x + (size_t)m * DMODEL;

    float v0 = xr[t]       + rr[t]       + fb[t];
    float v1 = xr[t + 256] + rr[t + 256] + fb[t + 256];
    float s = v0 + v1;
    float q = v0 * v0 + v1 * v1;
#pragma unroll
    for (int o = 16; o > 0; o >>= 1) {
        s += __shfl_xor_sync(0xffffffffu, s, o);
        q += __shfl_xor_sync(0xffffffffu, q, o);
    }
    __shared__ float ss[8], qs[8];
    __shared__ float mu_s, inv_s;
    if ((t & 31) == 0) { ss[t >> 5] = s; qs[t >> 5] = q; }
    __syncthreads();
    if (t == 0) {
        float S = 0.f, Q = 0.f;
#pragma unroll
        for (int i = 0; i < 8; i++) { S += ss[i]; Q += qs[i]; }
        float mu = S * (1.0f / DMODEL);
        float var = Q * (1.0f / DMODEL) - mu * mu;
        mu_s = mu;
        inv_s = rsqrtf(var + 1e-5f);
    }
    __syncthreads();
    const float mu = mu_s, inv = inv_s;
    out[(size_t)m * DMODEL + t]       = (v0 - mu) * inv * lg[t]       + lb[t];
    out[(size_t)m * DMODEL + t + 256] = (v1 - mu) * inv * lg[t + 256] + lb[t + 256];
}

// ------------------------------ host launcher -------------------------------
template<typename T>
static T* symaddr(const void* sym) {
    void* p = nullptr;
    cudaGetSymbolAddress(&p, sym);
    return reinterpret_cast<T*>(p);
}

extern "C" void kernel_launch(void* const* d_in, const int* in_sizes, int n_in,
                              void* d_out, int out_size)
{
    // Resolve input ordering: f_in_w = 1048576, fusion_w = 524288
    int fi, bi, i_fw, i_fb, i_lg, i_lb;
    if (in_sizes[1] == 2048 * 512) {          // signature order
        fi = 1; bi = 10; i_fw = 19; i_fb = 20; i_lg = 21; i_lb = 22;
    } else {                                  // dict order
        i_fw = 1; i_fb = 2; i_lg = 3; i_lb = 4; fi = 5; bi = 14;
    }

    const float* x        = (const float*)d_in[0];
    const float* f_in_w   = (const float*)d_in[fi + 0];
    const float* f_conv_w = (const float*)d_in[fi + 1];
    const float* f_conv_b = (const float*)d_in[fi + 2];
    const float* f_xproj  = (const float*)d_in[fi + 3];
    const float* f_dt_w   = (const float*)d_in[fi + 4];
    const float* f_dt_b   = (const float*)d_in[fi + 5];
    const float* f_A_log  = (const float*)d_in[fi + 6];
    const float* f_D      = (const float*)d_in[fi + 7];
    const float* f_out_w  = (const float*)d_in[fi + 8];
    const float* b_in_w   = (const float*)d_in[bi + 0];
    const float* b_conv_w = (const float*)d_in[bi + 1];
    const float* b_conv_b = (const float*)d_in[bi + 2];
    const float* b_xproj  = (const float*)d_in[bi + 3];
    const float* b_dt_w   = (const float*)d_in[bi + 4];
    const float* b_dt_b   = (const float*)d_in[bi + 5];
    const float* b_A_log  = (const float*)d_in[bi + 6];
    const float* b_D      = (const float*)d_in[bi + 7];
    const float* b_out_w  = (const float*)d_in[bi + 8];
    const float* fusion_w = (const float*)d_in[i_fw];
    const float* fusion_b = (const float*)d_in[i_fb];
    const float* ln_g     = (const float*)d_in[i_lg];
    const float* ln_b     = (const float*)d_in[i_lb];
    float* out = (float*)d_out;

    float* xdbl   = symaddr<float>(g_xdbl);
    float* delta  = symaddr<float>(g_delta);
    float* rbuf   = symaddr<float>(g_r);
    float* xpart  = symaddr<float>(g_xpart);
    float* aval   = symaddr<float>(g_Aval);
    __nv_bfloat16* xz    = symaddr<__nv_bfloat16>(g_xz);
    __nv_bfloat16* xhi   = symaddr<__nv_bfloat16>(g_xhi);
    __nv_bfloat16* wihi  = symaddr<__nv_bfloat16>(g_wihi);
    __nv_bfloat16* wohi  = symaddr<__nv_bfloat16>(g_wohi);
    __nv_bfloat16* fwhi  = symaddr<__nv_bfloat16>(g_fwhi);
    __nv_bfloat16* xpwhi = symaddr<__nv_bfloat16>(g_xpwhi);
    __nv_bfloat16* xpwlo = symaddr<__nv_bfloat16>(g_xpwlo);
    __nv_bfloat16* xihi  = symaddr<__nv_bfloat16>(g_xihi);
    __nv_bfloat16* yhi   = symaddr<__nv_bfloat16>(g_yhi);
    __nv_bfloat16* fuhi  = symaddr<__nv_bfloat16>(g_fuhi);

    const size_t XI_D = (size_t)MROWS * DINNER;
    const size_t XPART_DIR = (size_t)XKS * MROWS * 64;   // per-dir stride in xpart
    const size_t XPART_KS  = (size_t)MROWS * 64;         // per-slice stride

    // 0) fused prep: bf16 conversions + A' = -exp(A_log)*log2e
    PrepJobs J;
    const int nX  = MROWS * DMODEL / 4;
    const int nWI = WI_SZ / 4, nWO = WO_SZ / 4, nFW = FW_SZ / 4, nXP = XPW_SZ / 4;
    const int nAL = (DINNER * DSTATE) / 4;
    for (int k = 0; k < 10; k++) { J.lo[k] = nullptr; J.fo[k] = nullptr; }
    J.src[0] = (const float4*)x;        J.hi[0] = (ushort4*)xhi;
    J.src[1] = (const float4*)f_in_w;   J.hi[1] = (ushort4*)wihi;
    J.src[2] = (const float4*)b_in_w;   J.hi[2] = (ushort4*)(wihi + WI_SZ);
    J.src[3] = (const float4*)f_out_w;  J.hi[3] = (ushort4*)wohi;
    J.src[4] = (const float4*)b_out_w;  J.hi[4] = (ushort4*)(wohi + WO_SZ);
    J.src[5] = (const float4*)fusion_w; J.hi[5] = (ushort4*)fwhi;
    J.src[6] = (const float4*)f_xproj;  J.hi[6] = (ushort4*)xpwhi;            J.lo[6] = (ushort4*)xpwlo;
    J.src[7] = (const float4*)b_xproj;  J.hi[7] = (ushort4*)(xpwhi + XPW_SZ); J.lo[7] = (ushort4*)(xpwlo + XPW_SZ);
    J.src[8] = (const float4*)f_A_log;  J.hi[8] = nullptr; J.fo[8] = (float4*)aval;
    J.src[9] = (const float4*)b_A_log;  J.hi[9] = nullptr; J.fo[9] = (float4*)(aval + DINNER * DSTATE);
    int e = 0;
    e += nX;  J.end4[0] = e;
    e += nWI; J.end4[1] = e;
    e += nWI; J.end4[2] = e;
    e += nWO; J.end4[3] = e;
    e += nWO; J.end4[4] = e;
    e += nFW; J.end4[5] = e;
    e += nXP; J.end4[6] = e;
    e += nXP; J.end4[7] = e;
    e += nAL; J.end4[8] = e;
    e += nAL; J.end4[9] = e;
    prep_all_kernel<<<(e + 255) / 256, 256>>>(J);

    // 1) in_proj (HMMA 1-pass, double-buffered): xz[dir] = x(_flip) @ in_w^T
    mma_gemm<true, false, 1, false, 1><<<dim3(32, 16, 2), 128>>>(
        xhi, wihi, nullptr, wihi + WI_SZ, nullptr,
        nullptr, xz, 0, (size_t)MROWS * 2 * DINNER, 0,
        DMODEL, DMODEL, DMODEL, 2 * DINNER);

    // 2) causal depthwise conv + SiLU -> xihi
    conv_silu_kernel<<<dim3(128, 4), 256>>>(f_conv_w, f_conv_b, b_conv_w, b_conv_b);

    // 3) xproj (HMMA 2-pass B-split, split-K8): partials into g_xpart
    mma_gemm<false, false, 0, true, XKS><<<dim3(1, 16, 2 * XKS), 128>>>(
        xihi, xpwhi, xpwlo, xpwhi + XPW_SZ, xpwlo + XPW_SZ,
        xpart, nullptr, XI_D, XPART_DIR, XPART_KS,
        DINNER, DINNER, DINNER, 64);
    // reduce B/C columns only (scan inputs)
    xdbl_reduce_kernel<<<(2 * MROWS * 32) / 256, 256>>>();

    // 4) dtproj (SIMT, SUMKS fuses the dt-column reduce):
    //    delta = softplus( (Σ_ks xpart[:, 0:32]) @ dt_w^T + dt_b )
    gemm_nt<64, 64, 16, 4, 4, true, XKS>
        <<<dim3(16, 32, 2), 256>>>(xpart, f_dt_w, b_dt_w, delta, f_dt_b, b_dt_b,
                                   XPART_DIR, XI_D, XPART_KS,
                                   MROWS, DINNER, DTRANK, 64, DTRANK, DINNER);

    // 5) chunked selective scan (+ fused gating, emits yhi)
    scanA_kernel<<<dim3(32, CH, 4), 128>>>();
    scanB_kernel<<<128, 128>>>();
    scanC_kernel<<<dim3(32, CH, 4), 128>>>(f_D, b_D);

    // 6) out_proj (HMMA 1-pass, double-buffered): fusein = y @ out_w^T
    mma_gemm<false, true, 1, false, 1><<<dim3(8, 16, 2), 128>>>(
        yhi, wohi, nullptr, wohi + WO_SZ, nullptr,
        nullptr, fuhi, XI_D, (size_t)DMODEL, 0,
        DINNER, DINNER, DINNER, 2 * DMODEL);

    // 7) fusion (HMMA 1-pass, double-buffered): r = fused @ fusion_w^T
    mma_gemm<false, false, 0, false, 1><<<dim3(8, 16, 1), 128>>>(
        fuhi, fwhi, nullptr, fwhi, nullptr,
        rbuf, nullptr, 0, 0, 0,
        2 * DMODEL, 2 * DMODEL, 2 * DMODEL, DMODEL);

    // 8) residual + bias + layernorm -> d_out
    ln_kernel<<<MROWS, 256>>>(x, fusion_b, ln_g, ln_b, out);

    (void)n_in; (void)out_size;
}

// round 15
// speedup vs baseline: 1.0439x; 1.0439x over previous
#include <cuda_runtime.h>
#include <cuda_bf16.h>
#include <cstdint>
#include <cstddef>

// ---------------------------------------------------------------------------
// BidirectionalMambaBlock — HMMA bf16 GEMMs (double-buffered 1-pass big /
// double-buffered 2-pass xproj splitK4) + chunked scan   [R13 base]
// ---------------------------------------------------------------------------

#define L_SEQ   1024
#define BATCH   2
#define DMODEL  512
#define DINNER  1024
#define DSTATE  16
#define DTRANK  32
#define MROWS   (BATCH * L_SEQ)     // 2048
#define CH      8
#define TC      (L_SEQ / CH)        // 128
#define XKS     4                   // split-K for xproj (HMMA)

#define WI_SZ   (2 * DINNER * DMODEL)
#define WO_SZ   (DMODEL * DINNER)
#define FW_SZ   (DMODEL * 2 * DMODEL)
#define XPW_SZ  (64 * DINNER)

// ------------------------- scratch (device globals) ------------------------
__device__ float g_xdbl[(size_t)2 * MROWS * 64];
__device__ float g_xpart[(size_t)2 * XKS * MROWS * 64];
__device__ float g_delta[(size_t)2 * MROWS * DINNER];
__device__ float g_r[(size_t)MROWS * DMODEL];
__device__ float g_Aval[2 * DINNER * DSTATE];
__device__ float g_hpart[(size_t)4 * CH * DINNER * DSTATE];
__device__ float g_hin[(size_t)4 * CH * DINNER * DSTATE];
__device__ float g_sumd[(size_t)4 * CH * DINNER];

// bf16 operands / intermediates (16B-aligned)
__device__ __align__(128) __nv_bfloat16 g_xz[(size_t)2 * MROWS * 2 * DINNER];
__device__ __align__(128) __nv_bfloat16 g_xhi[(size_t)MROWS * DMODEL];
__device__ __align__(128) __nv_bfloat16 g_wihi[(size_t)2 * WI_SZ];
__device__ __align__(128) __nv_bfloat16 g_wohi[(size_t)2 * WO_SZ];
__device__ __align__(128) __nv_bfloat16 g_fwhi[(size_t)FW_SZ];
__device__ __align__(128) __nv_bfloat16 g_xpwhi[(size_t)2 * XPW_SZ];
__device__ __align__(128) __nv_bfloat16 g_xpwlo[(size_t)2 * XPW_SZ];
__device__ __align__(128) __nv_bfloat16 g_xihi[(size_t)2 * MROWS * DINNER];
__device__ __align__(128) __nv_bfloat16 g_yhi[(size_t)2 * MROWS * DINNER];
__device__ __align__(128) __nv_bfloat16 g_fuhi[(size_t)MROWS * 2 * DMODEL];

// ------------------------------ device helpers -----------------------------
__device__ __forceinline__ float2 ffma2(float2 a, float2 b, float2 c) {
    unsigned long long ua = *reinterpret_cast<unsigned long long*>(&a);
    unsigned long long ub = *reinterpret_cast<unsigned long long*>(&b);
    unsigned long long uc = *reinterpret_cast<unsigned long long*>(&c);
    unsigned long long ud;
    asm("fma.rn.f32x2 %0, %1, %2, %3;" : "=l"(ud) : "l"(ua), "l"(ub), "l"(uc));
    return *reinterpret_cast<float2*>(&ud);
}
__device__ __forceinline__ float ex2f(float x) {
    float y; asm("ex2.approx.ftz.f32 %0, %1;" : "=f"(y) : "f"(x)); return y;
}
__device__ __forceinline__ float softplusf(float x) {
    return (x > 15.0f) ? x : __logf(1.0f + __expf(x));
}
__device__ __forceinline__ float siluf(float x) {
    return __fdividef(x, 1.0f + __expf(-x));
}
__device__ __forceinline__ uint32_t smem_u32(const void* p) {
    uint32_t a;
    asm("{ .reg .u64 t; cvta.to.shared.u64 t, %1; cvt.u32.u64 %0, t; }" : "=r"(a) : "l"(p));
    return a;
}
__device__ __forceinline__ void ldsm4(uint32_t* r, uint32_t addr) {
    asm volatile("ldmatrix.sync.aligned.m8n8.x4.shared.b16 {%0,%1,%2,%3}, [%4];"
                 : "=r"(r[0]), "=r"(r[1]), "=r"(r[2]), "=r"(r[3]) : "r"(addr));
}
__device__ __forceinline__ void mma_bf16(float* c, const uint32_t* a, const uint32_t* b) {
    asm volatile(
        "mma.sync.aligned.m16n8k16.row.col.f32.bf16.bf16.f32 "
        "{%0,%1,%2,%3}, {%4,%5,%6,%7}, {%8,%9}, {%0,%1,%2,%3};"
        : "+f"(c[0]), "+f"(c[1]), "+f"(c[2]), "+f"(c[3])
        : "r"(a[0]), "r"(a[1]), "r"(a[2]), "r"(a[3]), "r"(b[0]), "r"(b[1]));
}
__device__ __forceinline__ unsigned short bits(__nv_bfloat16 v) {
    return *reinterpret_cast<unsigned short*>(&v);
}
__device__ __forceinline__ float bf2f(__nv_bfloat16 v) { return __bfloat162float(v); }
__device__ __forceinline__ float4 ld4bf(const __nv_bfloat16* p) {
    ushort4 u = *reinterpret_cast<const ushort4*>(p);
    float4 f;
    f.x = bf2f(*reinterpret_cast<__nv_bfloat16*>(&u.x));
    f.y = bf2f(*reinterpret_cast<__nv_bfloat16*>(&u.y));
    f.z = bf2f(*reinterpret_cast<__nv_bfloat16*>(&u.z));
    f.w = bf2f(*reinterpret_cast<__nv_bfloat16*>(&u.w));
    return f;
}

// ------------- fused prep: bf16 hi(/lo) conversions + A' segments -----------
struct PrepJobs {
    const float4* src[10];
    ushort4* hi[10];
    ushort4* lo[10];   // nullptr -> no lo plane
    float4* fo[10];    // non-null -> A' mode: out = -exp(v)*log2e (fp32)
    int end4[10];
};

__global__ void prep_all_kernel(PrepJobs J)
{
    const int i = blockIdx.x * 256 + threadIdx.x;
    if (i >= J.end4[9]) return;
    int s = 0;
#pragma unroll
    for (int k = 0; k < 9; k++) s += (i >= J.end4[k]) ? 1 : 0;
    const int base = s ? J.end4[s - 1] : 0;
    const int off = i - base;

    const float4 v = J.src[s][off];
    if (J.fo[s]) {
        float4 o;
        o.x = -__expf(v.x) * 1.4426950408889634f;
        o.y = -__expf(v.y) * 1.4426950408889634f;
        o.z = -__expf(v.z) * 1.4426950408889634f;
        o.w = -__expf(v.w) * 1.4426950408889634f;
        J.fo[s][off] = o;
        return;
    }
    __nv_bfloat16 h0 = __float2bfloat16(v.x), h1 = __float2bfloat16(v.y);
    __nv_bfloat16 h2 = __float2bfloat16(v.z), h3 = __float2bfloat16(v.w);
    ushort4 uh; uh.x = bits(h0); uh.y = bits(h1); uh.z = bits(h2); uh.w = bits(h3);
    J.hi[s][off] = uh;
    if (J.lo[s]) {
        ushort4 ul;
        ul.x = bits(__float2bfloat16(v.x - bf2f(h0)));
        ul.y = bits(__float2bfloat16(v.y - bf2f(h1)));
        ul.z = bits(__float2bfloat16(v.z - bf2f(h2)));
        ul.w = bits(__float2bfloat16(v.w - bf2f(h3)));
        J.lo[s][off] = ul;
    }
}

// -------------------- HMMA bf16 GEMM (NT), dir-batched ----------------------
// FAST (!BSPLIT): 1-pass, double-buffered smem, 1 sync/chunk.
// BSPLIT: 2-pass B hi/lo (A hi only), double-buffered, 1 sync/chunk (xproj).
// CTA tile 128x64, BK=32, 4 warps. blockIdx.z = dir*KS + ks.
// OUTMODE 0: fp32 C; 1: bf16 hi C.
template<bool FLIPA, bool FLIPSTORE, int OUTMODE, bool BSPLIT, int KS>
__global__ void __launch_bounds__(128)
mma_gemm(const __nv_bfloat16* __restrict__ Ahi,
         const __nv_bfloat16* __restrict__ Bhi0, const __nv_bfloat16* __restrict__ Blo0,
         const __nv_bfloat16* __restrict__ Bhi1, const __nv_bfloat16* __restrict__ Blo1,
         float* __restrict__ Cf, __nv_bfloat16* __restrict__ Chi,
         size_t aStride, size_t cStride, size_t sliceStride,
         int K, int lda, int ldb, int ldc)
{
    // FAST: sB[buf]. BSPLIT: sB[buf*2 + plane] (hi/lo).
    __shared__ __align__(16) __nv_bfloat16 sA[2][128][40];
    __shared__ __align__(16) __nv_bfloat16 sB[BSPLIT ? 4 : 2][64][40];

    const int tid = threadIdx.x;
    const int warp = tid >> 5, lane = tid & 31;
    const int wm = warp >> 1, wn = warp & 1;
    const int z = blockIdx.z;
    const int dir = z / KS, ks = z % KS;
    const int bm = blockIdx.y * 128, bn = blockIdx.x * 64;

    const __nv_bfloat16* __restrict__ Bh = dir ? Bhi1 : Bhi0;
    const __nv_bfloat16* __restrict__ Bl = dir ? Blo1 : Blo0;
    Ahi += (size_t)dir * aStride;

    const int kBase = ks * (K / KS);
    const int nCh = (K / KS) >> 5;

    float acc[4][4][4];
#pragma unroll
    for (int i = 0; i < 4; i++)
#pragma unroll
        for (int j = 0; j < 4; j++)
#pragma unroll
            for (int e = 0; e < 4; e++) acc[i][j][e] = 0.0f;

    const int arow = wm * 64 + (lane & 15);
    const int acol = (lane >> 4) << 3;
    const int brow = wn * 32 + ((lane >> 4) << 3) + (lane & 7);
    const int bcol = ((lane >> 3) & 1) << 3;

    const uint32_t sa0 = smem_u32(&sA[0][0][0]);
    const uint32_t sa1 = smem_u32(&sA[1][0][0]);

    if (!BSPLIT) {
        const uint32_t sb0 = smem_u32(&sB[0][0][0]);
        const uint32_t sb1 = smem_u32(&sB[1][0][0]);
        uint4 ra[4], rb[2];
#pragma unroll
        for (int i = 0; i < 4; i++) {
            const int idx = i * 128 + tid, row = idx >> 2, q = idx & 3;
            int gr = bm + row; if (FLIPA && dir) gr ^= (L_SEQ - 1);
            ra[i] = *reinterpret_cast<const uint4*>(Ahi + (size_t)gr * lda + kBase + q * 8);
        }
#pragma unroll
        for (int i = 0; i < 2; i++) {
            const int idx = i * 128 + tid, row = idx >> 2, q = idx & 3;
            rb[i] = *reinterpret_cast<const uint4*>(Bh + (size_t)(bn + row) * ldb + kBase + q * 8);
        }
#pragma unroll
        for (int i = 0; i < 4; i++) {
            const int idx = i * 128 + tid, row = idx >> 2, q = idx & 3;
            *reinterpret_cast<uint4*>(&sA[0][row][q * 8]) = ra[i];
        }
#pragma unroll
        for (int i = 0; i < 2; i++) {
            const int idx = i * 128 + tid, row = idx >> 2, q = idx & 3;
            *reinterpret_cast<uint4*>(&sB[0][row][q * 8]) = rb[i];
        }
        if (nCh > 1) {
            const int k0 = kBase + 32;
#pragma unroll
            for (int i = 0; i < 4; i++) {
                const int idx = i * 128 + tid, row = idx >> 2, q = idx & 3;
                int gr = bm + row; if (FLIPA && dir) gr ^= (L_SEQ - 1);
                ra[i] = *reinterpret_cast<const uint4*>(Ahi + (size_t)gr * lda + k0 + q * 8);
            }
#pragma unroll
            for (int i = 0; i < 2; i++) {
                const int idx = i * 128 + tid, row = idx >> 2, q = idx & 3;
                rb[i] = *reinterpret_cast<const uint4*>(Bh + (size_t)(bn + row) * ldb + k0 + q * 8);
            }
        }
        __syncthreads();

        for (int ch = 0; ch < nCh; ++ch) {
            const int cur = ch & 1, nxt = cur ^ 1;
            if (ch + 1 < nCh) {
#pragma unroll
                for (int i = 0; i < 4; i++) {
                    const int idx = i * 128 + tid, row = idx >> 2, q = idx & 3;
                    *reinterpret_cast<uint4*>(&sA[nxt][row][q * 8]) = ra[i];
                }
#pragma unroll
                for (int i = 0; i < 2; i++) {
                    const int idx = i * 128 + tid, row = idx >> 2, q = idx & 3;
                    *reinterpret_cast<uint4*>(&sB[nxt][row][q * 8]) = rb[i];
                }
                if (ch + 2 < nCh) {
                    const int k0 = kBase + ((ch + 2) << 5);
#pragma unroll
                    for (int i = 0; i < 4; i++) {
                        const int idx = i * 128 + tid, row = idx >> 2, q = idx & 3;
                        int gr = bm + row; if (FLIPA && dir) gr ^= (L_SEQ - 1);
                        ra[i] = *reinterpret_cast<const uint4*>(Ahi + (size_t)gr * lda + k0 + q * 8);
                    }
#pragma unroll
                    for (int i = 0; i < 2; i++) {
                        const int idx = i * 128 + tid, row = idx >> 2, q = idx & 3;
                        rb[i] = *reinterpret_cast<const uint4*>(Bh + (size_t)(bn + row) * ldb + k0 + q * 8);
                    }
                }
            }
            const uint32_t sa = cur ? sa1 : sa0;
            const uint32_t sb = cur ? sb1 : sb0;
#pragma unroll
            for (int k16 = 0; k16 < 32; k16 += 16) {
                uint32_t ah[4][4], bh[2][4];
#pragma unroll
                for (int mi = 0; mi < 4; mi++)
                    ldsm4(ah[mi], sa + ((uint32_t)(arow + mi * 16) * 40 + k16 + acol) * 2);
#pragma unroll
                for (int p = 0; p < 2; p++)
                    ldsm4(bh[p], sb + ((uint32_t)(brow + p * 16) * 40 + k16 + bcol) * 2);
#pragma unroll
                for (int mi = 0; mi < 4; mi++)
#pragma unroll
                    for (int nj = 0; nj < 4; nj++)
                        mma_bf16(acc[mi][nj], ah[mi], &bh[nj >> 1][(nj & 1) * 2]);
            }
            __syncthreads();
        }
    } else {
        // ------- BSPLIT: 2-pass (A hi; B hi+lo), double-buffered ------------
        const uint32_t sbh0 = smem_u32(&sB[0][0][0]);
        const uint32_t sbl0 = smem_u32(&sB[1][0][0]);
        const uint32_t sbh1 = smem_u32(&sB[BSPLIT ? 2 : 0][0][0]);
        const uint32_t sbl1 = smem_u32(&sB[BSPLIT ? 3 : 0][0][0]);

        uint4 ra[4], rb[2][2];
#pragma unroll
        for (int i = 0; i < 4; i++) {
            const int idx = i * 128 + tid, row = idx >> 2, q = idx & 3;
            int gr = bm + row; if (FLIPA && dir) gr ^= (L_SEQ - 1);
            ra[i] = *reinterpret_cast<const uint4*>(Ahi + (size_t)gr * lda + kBase + q * 8);
        }
#pragma unroll
        for (int i = 0; i < 2; i++) {
            const int idx = i * 128 + tid, row = idx >> 2, q = idx & 3;
            const size_t off = (size_t)(bn + row) * ldb + kBase + q * 8;
            rb[0][i] = *reinterpret_cast<const uint4*>(Bh + off);
            rb[1][i] = *reinterpret_cast<const uint4*>(Bl + off);
        }
#pragma unroll
        for (int i = 0; i < 4; i++) {
            const int idx = i * 128 + tid, row = idx >> 2, q = idx & 3;
            *reinterpret_cast<uint4*>(&sA[0][row][q * 8]) = ra[i];
        }
#pragma unroll
        for (int i = 0; i < 2; i++) {
            const int idx = i * 128 + tid, row = idx >> 2, q = idx & 3;
            *reinterpret_cast<uint4*>(&sB[0][row][q * 8]) = rb[0][i];
            *reinterpret_cast<uint4*>(&sB[1][row][q * 8]) = rb[1][i];
        }
        if (nCh > 1) {
            const int k0 = kBase + 32;
#pragma unroll
            for (int i = 0; i < 4; i++) {
                const int idx = i * 128 + tid, row = idx >> 2, q = idx & 3;
                int gr = bm + row; if (FLIPA && dir) gr ^= (L_SEQ - 1);
                ra[i] = *reinterpret_cast<const uint4*>(Ahi + (size_t)gr * lda + k0 + q * 8);
            }
#pragma unroll
            for (int i = 0; i < 2; i++) {
                const int idx = i * 128 + tid, row = idx >> 2, q = idx & 3;
                const size_t off = (size_t)(bn + row) * ldb + k0 + q * 8;
                rb[0][i] = *reinterpret_cast<const uint4*>(Bh + off);
                rb[1][i] = *reinterpret_cast<const uint4*>(Bl + off);
            }
        }
        __syncthreads();

        for (int ch = 0; ch < nCh; ++ch) {
            const int cur = ch & 1, nxt = cur ^ 1;
            if (ch + 1 < nCh) {
#pragma unroll
                for (int i = 0; i < 4; i++) {
                    const int idx = i * 128 + tid, row = idx >> 2, q = idx & 3;
                    *reinterpret_cast<uint4*>(&sA[nxt][row][q * 8]) = ra[i];
                }
#pragma unroll
                for (int i = 0; i < 2; i++) {
                    const int idx = i * 128 + tid, row = idx >> 2, q = idx & 3;
                    *reinterpret_cast<uint4*>(&sB[nxt * 2 + 0][row][q * 8]) = rb[0][i];
                    *reinterpret_cast<uint4*>(&sB[nxt * 2 + 1][row][q * 8]) = rb[1][i];
                }
                if (ch + 2 < nCh) {
                    const int k0 = kBase + ((ch + 2) << 5);
#pragma unroll
                    for (int i = 0; i < 4; i++) {
                        const int idx = i * 128 + tid, row = idx >> 2, q = idx & 3;
                        int gr = bm + row; if (FLIPA && dir) gr ^= (L_SEQ - 1);
                        ra[i] = *reinterpret_cast<const uint4*>(Ahi + (size_t)gr * lda + k0 + q * 8);
                    }
#pragma unroll
                    for (int i = 0; i < 2; i++) {
                        const int idx = i * 128 + tid, row = idx >> 2, q = idx & 3;
                        const size_t off = (size_t)(bn + row) * ldb + k0 + q * 8;
                        rb[0][i] = *reinterpret_cast<const uint4*>(Bh + off);
                        rb[1][i] = *reinterpret_cast<const uint4*>(Bl + off);
                    }
                }
            }
            const uint32_t sa = cur ? sa1 : sa0;
            const uint32_t sbh = cur ? sbh1 : sbh0;
            const uint32_t sbl = cur ? sbl1 : sbl0;
#pragma unroll
            for (int k16 = 0; k16 < 32; k16 += 16) {
                uint32_t ah[4][4], bh[2][4], bl[2][4];
#pragma unroll
                for (int mi = 0; mi < 4; mi++)
                    ldsm4(ah[mi], sa + ((uint32_t)(arow + mi * 16) * 40 + k16 + acol) * 2);
#pragma unroll
                for (int p = 0; p < 2; p++) {
                    const uint32_t off = ((uint32_t)(brow + p * 16) * 40 + k16 + bcol) * 2;
                    ldsm4(bh[p], sbh + off);
                    ldsm4(bl[p], sbl + off);
                }
#pragma unroll
                for (int mi = 0; mi < 4; mi++)
#pragma unroll
                    for (int nj = 0; nj < 4; nj++) {
                        mma_bf16(acc[mi][nj], ah[mi], &bh[nj >> 1][(nj & 1) * 2]);
                        mma_bf16(acc[mi][nj], ah[mi], &bl[nj >> 1][(nj & 1) * 2]);
                    }
            }
            __syncthreads();
        }
    }

    // epilogue
    if (OUTMODE == 0) Cf += (size_t)dir * cStride + (size_t)ks * sliceStride;
    else Chi += (size_t)dir * cStride;

#pragma unroll
    for (int mi = 0; mi < 4; mi++) {
#pragma unroll
        for (int nj = 0; nj < 4; nj++) {
            const int col = bn + wn * 32 + nj * 8 + (lane & 3) * 2;
            int r0 = bm + wm * 64 + mi * 16 + (lane >> 2);
            int r1 = r0 + 8;
            if (FLIPSTORE && dir) { r0 ^= (L_SEQ - 1); r1 ^= (L_SEQ - 1); }
            const float* a = acc[mi][nj];
            if (OUTMODE == 0) {
                *reinterpret_cast<float2*>(Cf + (size_t)r0 * ldc + col) = make_float2(a[0], a[1]);
                *reinterpret_cast<float2*>(Cf + (size_t)r1 * ldc + col) = make_float2(a[2], a[3]);
            } else {
                ushort2 u0, u1;
                u0.x = bits(__float2bfloat16(a[0]));
                u0.y = bits(__float2bfloat16(a[1]));
                u1.x = bits(__float2bfloat16(a[2]));
                u1.y = bits(__float2bfloat16(a[3]));
                *reinterpret_cast<ushort2*>(Chi + (size_t)r0 * ldc + col) = u0;
                *reinterpret_cast<ushort2*>(Chi + (size_t)r1 * ldc + col) = u1;
            }
        }
    }
}

// ---------------- pipelined SIMT SGEMM (NT) — dtproj only -------------------
template<int BM, int BN, int BK, int TM, int TN, bool SOFTPLUS>
__global__ void __launch_bounds__((BM / TM) * (BN / TN))
gemm_nt(const float* __restrict__ A, const float* __restrict__ B0,
        const float* __restrict__ B1, float* __restrict__ C,
        const float* __restrict__ bias0, const float* __restrict__ bias1,
        size_t aStride, size_t cStride,
        int M, int N, int K, int lda, int ldb, int ldc)
{
    constexpr int NTHR = (BM / TM) * (BN / TN);
    constexpr int TX = BN / TN;
    constexpr int PAD = 4;
    constexpr int AKT = BK / 4;
    constexpr int ALD = (BM * BK) / (NTHR * 4);
    constexpr int BLD = (BN * BK) / (NTHR * 4);
    constexpr int ARS = NTHR / AKT;

    __shared__ __align__(16) float As[2][BK][BM + PAD];
    __shared__ __align__(16) float Bs[2][BK][BN + PAD];

    const int dir = blockIdx.z;
    const float* __restrict__ Bw = dir ? B1 : B0;
    const float* __restrict__ bias = dir ? bias1 : bias0;
    A += (size_t)dir * aStride;
    C += (size_t)dir * cStride;

    const int tid = threadIdx.x;
    const int bn = blockIdx.x * BN;
    const int bm = blockIdx.y * BM;
    const int tx = tid % TX;
    const int ty = tid / TX;
    const int ar = tid / AKT;
    const int ac = (tid % AKT) * 4;

    const int nIter = K / BK;

    float2 acc[TM][TN / 2];
#pragma unroll
    for (int i = 0; i < TM; i++)
#pragma unroll
        for (int j = 0; j < TN / 2; j++) acc[i][j] = make_float2(0.0f, 0.0f);

    float4 ra[ALD], rb[BLD];

#pragma unroll
    for (int i = 0; i < ALD; i++)
        ra[i] = *reinterpret_cast<const float4*>(A + (size_t)(bm + ar + i * ARS) * lda + ac);
#pragma unroll
    for (int i = 0; i < BLD; i++)
        rb[i] = *reinterpret_cast<const float4*>(Bw + (size_t)(bn + ar + i * ARS) * ldb + ac);

#pragma unroll
    for (int i = 0; i < ALD; i++) {
        int r = ar + i * ARS;
        As[0][ac + 0][r] = ra[i].x; As[0][ac + 1][r] = ra[i].y;
        As[0][ac + 2][r] = ra[i].z; As[0][ac + 3][r] = ra[i].w;
    }
#pragma unroll
    for (int i = 0; i < BLD; i++) {
        int r = ar + i * ARS;
        Bs[0][ac + 0][r] = rb[i].x; Bs[0][ac + 1][r] = rb[i].y;
        Bs[0][ac + 2][r] = rb[i].z; Bs[0][ac + 3][r] = rb[i].w;
    }
    __syncthreads();

    for (int it = 0; it < nIter; ++it) {
        const int cur = it & 1;
        const bool more = (it + 1 < nIter);
        if (more) {
            const int kg = (it + 1) * BK;
#pragma unroll
            for (int i = 0; i < ALD; i++)
                ra[i] = *reinterpret_cast<const float4*>(A + (size_t)(bm + ar + i * ARS) * lda + kg + ac);
#pragma unroll
            for (int i = 0; i < BLD; i++)
                rb[i] = *reinterpret_cast<const float4*>(Bw + (size_t)(bn + ar + i * ARS) * ldb + kg + ac);
        }

#pragma unroll
        for (int k = 0; k < BK; k++) {
            float a[TM];
            float2 b2[TN / 2];
#pragma unroll
            for (int i = 0; i < TM; i += 4) {
                float4 t = *reinterpret_cast<const float4*>(&As[cur][k][ty * TM + i]);
                a[i] = t.x; a[i + 1] = t.y; a[i + 2] = t.z; a[i + 3] = t.w;
            }
#pragma unroll
            for (int j = 0; j < TN; j += 4) {
                float4 t = *reinterpret_cast<const float4*>(&Bs[cur][k][tx * TN + j]);
                b2[j / 2]     = make_float2(t.x, t.y);
                b2[j / 2 + 1] = make_float2(t.z, t.w);
            }
#pragma unroll
            for (int i = 0; i < TM; i++) {
                float2 a2 = make_float2(a[i], a[i]);
#pragma unroll
                for (int j = 0; j < TN / 2; j++)
                    acc[i][j] = ffma2(a2, b2[j], acc[i][j]);
            }
        }

        if (more) {
            const int nxt = cur ^ 1;
#pragma unroll
            for (int i = 0; i < ALD; i++) {
                int r = ar + i * ARS;
                As[nxt][ac + 0][r] = ra[i].x; As[nxt][ac + 1][r] = ra[i].y;
                As[nxt][ac + 2][r] = ra[i].z; As[nxt][ac + 3][r] = ra[i].w;
            }
#pragma unroll
            for (int i = 0; i < BLD; i++) {
                int r = ar + i * ARS;
                Bs[nxt][ac + 0][r] = rb[i].x; Bs[nxt][ac + 1][r] = rb[i].y;
                Bs[nxt][ac + 2][r] = rb[i].z; Bs[nxt][ac + 3][r] = rb[i].w;
            }
            __syncthreads();
        }
    }

#pragma unroll
    for (int i = 0; i < TM; i++) {
        int m = bm + ty * TM + i;
#pragma unroll
        for (int j = 0; j < TN / 2; j++) {
            int n = bn + tx * TN + 2 * j;
            float2 v = acc[i][j];
            if (SOFTPLUS) {
                v.x = softplusf(v.x + bias[n]);
                v.y = softplusf(v.y + bias[n + 1]);
            }
            *reinterpret_cast<float2*>(C + (size_t)m * ldc + n) = v;
        }
    }
}

// ----------------- split-K reduce for xproj partials ------------------------
__global__ void xdbl_reduce_kernel()
{
    const int idx = blockIdx.x * 256 + threadIdx.x;
    const size_t per = (size_t)MROWS * 64;
    const int dir = idx / (int)per;
    const size_t off = (size_t)idx - (size_t)dir * per;
    float s = 0.0f;
#pragma unroll
    for (int ks = 0; ks < XKS; ks++)
        s += g_xpart[((size_t)dir * XKS + ks) * per + off];
    g_xdbl[(size_t)dir * per + off] = s;
}

// -------- causal depthwise conv + SiLU (rolling 8-step) -> bf16 hi ----------
__global__ void conv_silu_kernel(const float* __restrict__ cwf, const float* __restrict__ cbf,
                                 const float* __restrict__ cwb, const float* __restrict__ cbb)
{
    const int tb   = blockIdx.x;
    const int dirb = blockIdx.y;
    const int dir = dirb >> 1, b = dirb & 1;
    const int l0 = tb * 8;
    const int d0 = threadIdx.x * 4;
    const float* cw = dir ? cwb : cwf;
    const float* cb = dir ? cbb : cbf;

    float4 w0 = *reinterpret_cast<const float4*>(cw + (size_t)(d0 + 0) * 4);
    float4 w1 = *reinterpret_cast<const float4*>(cw + (size_t)(d0 + 1) * 4);
    float4 w2 = *reinterpret_cast<const float4*>(cw + (size_t)(d0 + 2) * 4);
    float4 w3 = *reinterpret_cast<const float4*>(cw + (size_t)(d0 + 3) * 4);
    const float4 bias = *reinterpret_cast<const float4*>(cb + d0);

    const size_t base = ((size_t)dir * MROWS + (size_t)b * L_SEQ) * (2 * DINNER) + d0;
    const float4 zero = make_float4(0.f, 0.f, 0.f, 0.f);

    float4 xm3 = (l0 - 3 >= 0) ? ld4bf(g_xz + base + (size_t)(l0 - 3) * (2 * DINNER)) : zero;
    float4 xm2 = (l0 - 2 >= 0) ? ld4bf(g_xz + base + (size_t)(l0 - 2) * (2 * DINNER)) : zero;
    float4 xm1 = (l0 - 1 >= 0) ? ld4bf(g_xz + base + (size_t)(l0 - 1) * (2 * DINNER)) : zero;

    const size_t obase = ((size_t)dir * MROWS + (size_t)b * L_SEQ + l0) * DINNER + d0;

#pragma unroll
    for (int i = 0; i < 8; i++) {
        float4 xc = ld4bf(g_xz + base + (size_t)(l0 + i) * (2 * DINNER));
        float4 acc = bias;
        acc.x = fmaf(w0.x, xm3.x, fmaf(w0.y, xm2.x, fmaf(w0.z, xm1.x, fmaf(w0.w, xc.x, acc.x))));
        acc.y = fmaf(w1.x, xm3.y, fmaf(w1.y, xm2.y, fmaf(w1.z, xm1.y, fmaf(w1.w, xc.y, acc.y))));
        acc.z = fmaf(w2.x, xm3.z, fmaf(w2.y, xm2.z, fmaf(w2.z, xm1.z, fmaf(w2.w, xc.z, acc.z))));
        acc.w = fmaf(w3.x, xm3.w, fmaf(w3.y, xm2.w, fmaf(w3.z, xm1.w, fmaf(w3.w, xc.w, acc.w))));
        float4 o;
        o.x = siluf(acc.x); o.y = siluf(acc.y);
        o.z = siluf(acc.z); o.w = siluf(acc.w);

        ushort4 uh;
        uh.x = bits(__float2bfloat16(o.x));
        uh.y = bits(__float2bfloat16(o.y));
        uh.z = bits(__float2bfloat16(o.z));
        uh.w = bits(__float2bfloat16(o.w));
        *reinterpret_cast<ushort4*>(g_xihi + obase + (size_t)i * DINNER) = uh;

        xm3 = xm2; xm2 = xm1; xm1 = xc;
    }
}

// ------------------------------ chunked selective scan ----------------------
__global__ void scanA_kernel()
{
    const int db  = blockIdx.z;
    const int dir = db >> 1, b = db & 1;
    const int c   = blockIdx.y;
    const int t   = threadIdx.x;
    const int g4  = t & 3;
    const int d   = blockIdx.x * 32 + (t >> 2);

    const size_t rb = ((size_t)dir * MROWS + (size_t)b * L_SEQ + (size_t)c * TC) * DINNER + d;
    const float* __restrict__ dp = g_delta + rb;
    const __nv_bfloat16* __restrict__ xp = g_xihi + rb;
    const size_t xb = ((size_t)dir * MROWS + (size_t)b * L_SEQ + (size_t)c * TC) * 64;
    const float4* __restrict__ Bp = reinterpret_cast<const float4*>(g_xdbl + xb + 32) + g4;

    const float* ap = g_Aval + ((size_t)dir * DINNER + d) * DSTATE + 4 * g4;
    const float a0 = ap[0], a1 = ap[1], a2 = ap[2], a3 = ap[3];

    float h0 = 0.f, h1 = 0.f, h2 = 0.f, h3 = 0.f, sd = 0.f;

    for (int l = 0; l < TC; l++) {
        const float dlt = dp[(size_t)l * DINNER];
        const float xiv = bf2f(xp[(size_t)l * DINNER]);
        const float4 Bv = Bp[l * 16];
        const float u = dlt * xiv;
        h0 = fmaf(ex2f(dlt * a0), h0, u * Bv.x);
        h1 = fmaf(ex2f(dlt * a1), h1, u * Bv.y);
        h2 = fmaf(ex2f(dlt * a2), h2, u * Bv.z);
        h3 = fmaf(ex2f(dlt * a3), h3, u * Bv.w);
        sd += dlt;
    }
    const size_t hi = (((size_t)db * CH + c) * DINNER + d) * DSTATE + 4 * g4;
    float4 hv; hv.x = h0; hv.y = h1; hv.z = h2; hv.w = h3;
    *reinterpret_cast<float4*>(g_hpart + hi) = hv;
    if (g4 == 0) g_sumd[((size_t)db * CH + c) * DINNER + d] = sd;
}

__global__ void scanB_kernel()
{
    const int idx = blockIdx.x * 128 + threadIdx.x;
    const int g4 = idx & 3;
    const int d  = (idx >> 2) & (DINNER - 1);
    const int db = idx >> 12;
    const int dir = db >> 1;

    const float* ap = g_Aval + ((size_t)dir * DINNER + d) * DSTATE + 4 * g4;
    const float a0 = ap[0], a1 = ap[1], a2 = ap[2], a3 = ap[3];

    float h0 = 0.f, h1 = 0.f, h2 = 0.f, h3 = 0.f;
#pragma unroll
    for (int c = 0; c < CH; c++) {
        const size_t hi = (((size_t)db * CH + c) * DINNER + d) * DSTATE + 4 * g4;
        float4 hv; hv.x = h0; hv.y = h1; hv.z = h2; hv.w = h3;
        *reinterpret_cast<float4*>(g_hin + hi) = hv;
        const float S = g_sumd[((size_t)db * CH + c) * DINNER + d];
        const float4 hp = *reinterpret_cast<const float4*>(g_hpart + hi);
        h0 = fmaf(ex2f(S * a0), h0, hp.x);
        h1 = fmaf(ex2f(S * a1), h1, hp.y);
        h2 = fmaf(ex2f(S * a2), h2, hp.z);
        h3 = fmaf(ex2f(S * a3), h3, hp.w);
    }
}

__global__ void scanC_kernel(const float* __restrict__ Df, const float* __restrict__ Db)
{
    const int db  = blockIdx.z;
    const int dir = db >> 1, b = db & 1;
    const int c   = blockIdx.y;
    const int t   = threadIdx.x;
    const int g4  = t & 3;
    const int d   = blockIdx.x * 32 + (t >> 2);

    const size_t rb = ((size_t)dir * MROWS + (size_t)b * L_SEQ + (size_t)c * TC) * DINNER + d;
    const float* __restrict__ dp = g_delta + rb;
    const __nv_bfloat16* __restrict__ xp = g_xihi + rb;
    const size_t xb = ((size_t)dir * MROWS + (size_t)b * L_SEQ + (size_t)c * TC) * 64;
    const float4* __restrict__ Bp = reinterpret_cast<const float4*>(g_xdbl + xb + 32) + g4;
    const float4* __restrict__ Cp = reinterpret_cast<const float4*>(g_xdbl + xb + 48) + g4;
    const __nv_bfloat16* __restrict__ zp =
        g_xz + ((size_t)dir * MROWS + (size_t)b * L_SEQ + (size_t)c * TC) * (2 * DINNER) + DINNER + d;

    const float* ap = g_Aval + ((size_t)dir * DINNER + d) * DSTATE + 4 * g4;
    const float a0 = ap[0], a1 = ap[1], a2 = ap[2], a3 = ap[3];
    const float Dv = (dir ? Db : Df)[d];

    const size_t hi = (((size_t)db * CH + c) * DINNER + d) * DSTATE + 4 * g4;
    const float4 hin = *reinterpret_cast<const float4*>(g_hin + hi);
    float h0 = hin.x, h1 = hin.y, h2 = hin.z, h3 = hin.w;

    for (int l = 0; l < TC; l++) {
        const float dlt = dp[(size_t)l * DINNER];
        const float xiv = bf2f(xp[(size_t)l * DINNER]);
        const float4 Bv = Bp[l * 16];
        const float4 Cv = Cp[l * 16];
        const float u = dlt * xiv;
        h0 = fmaf(ex2f(dlt * a0), h0, u * Bv.x);
        h1 = fmaf(ex2f(dlt * a1), h1, u * Bv.y);
        h2 = fmaf(ex2f(dlt * a2), h2, u * Bv.z);
        h3 = fmaf(ex2f(dlt * a3), h3, u * Bv.w);
        float y = fmaf(h0, Cv.x, h1 * Cv.y) + fmaf(h2, Cv.z, h3 * Cv.w);
        y += __shfl_xor_sync(0xffffffffu, y, 1);
        y += __shfl_xor_sync(0xffffffffu, y, 2);
        if (g4 == 0) {
            const float z = bf2f(zp[(size_t)l * 2 * DINNER]);
            const float yv = fmaf(xiv, Dv, y) * siluf(z);
            g_yhi[rb + (size_t)l * DINNER] = __float2bfloat16(yv);
        }
    }
}

// ---------------- residual + fusion bias + LayerNorm ------------------------
__global__ void ln_kernel(const float* __restrict__ x, const float* __restrict__ fb,
                          const float* __restrict__ lg, const float* __restrict__ lb,
                          float* __restrict__ out)
{
    const int m = blockIdx.x;
    const int t = threadIdx.x;
    const float* rr = g_r + (size_t)m * DMODEL;
    const float* xr = x + (size_t)m * DMODEL;

    float v0 = xr[t]       + rr[t]       + fb[t];
    float v1 = xr[t + 256] + rr[t + 256] + fb[t + 256];
    float s = v0 + v1;
    float q = v0 * v0 + v1 * v1;
#pragma unroll
    for (int o = 16; o > 0; o >>= 1) {
        s += __shfl_xor_sync(0xffffffffu, s, o);
        q += __shfl_xor_sync(0xffffffffu, q, o);
    }
    __shared__ float ss[8], qs[8];
    __shared__ float mu_s, inv_s;
    if ((t & 31) == 0) { ss[t >> 5] = s; qs[t >> 5] = q; }
    __syncthreads();
    if (t == 0) {
        float S = 0.f, Q = 0.f;
#pragma unroll
        for (int i = 0; i < 8; i++) { S += ss[i]; Q += qs[i]; }
        float mu = S * (1.0f / DMODEL);
        float var = Q * (1.0f / DMODEL) - mu * mu;
        mu_s = mu;
        inv_s = rsqrtf(var + 1e-5f);
    }
    __syncthreads();
    const float mu = mu_s, inv = inv_s;
    out[(size_t)m * DMODEL + t]       = (v0 - mu) * inv * lg[t]       + lb[t];
    out[(size_t)m * DMODEL + t + 256] = (v1 - mu) * inv * lg[t + 256] + lb[t + 256];
}

// ------------------------------ host launcher -------------------------------
template<typename T>
static T* symaddr(const void* sym) {
    void* p = nullptr;
    cudaGetSymbolAddress(&p, sym);
    return reinterpret_cast<T*>(p);
}

extern "C" void kernel_launch(void* const* d_in, const int* in_sizes, int n_in,
                              void* d_out, int out_size)
{
    // Resolve input ordering: f_in_w = 1048576, fusion_w = 524288
    int fi, bi, i_fw, i_fb, i_lg, i_lb;
    if (in_sizes[1] == 2048 * 512) {          // signature order
        fi = 1; bi = 10; i_fw = 19; i_fb = 20; i_lg = 21; i_lb = 22;
    } else {                                  // dict order
        i_fw = 1; i_fb = 2; i_lg = 3; i_lb = 4; fi = 5; bi = 14;
    }

    const float* x        = (const float*)d_in[0];
    const float* f_in_w   = (const float*)d_in[fi + 0];
    const float* f_conv_w = (const float*)d_in[fi + 1];
    const float* f_conv_b = (const float*)d_in[fi + 2];
    const float* f_xproj  = (const float*)d_in[fi + 3];
    const float* f_dt_w   = (const float*)d_in[fi + 4];
    const float* f_dt_b   = (const float*)d_in[fi + 5];
    const float* f_A_log  = (const float*)d_in[fi + 6];
    const float* f_D      = (const float*)d_in[fi + 7];
    const float* f_out_w  = (const float*)d_in[fi + 8];
    const float* b_in_w   = (const float*)d_in[bi + 0];
    const float* b_conv_w = (const float*)d_in[bi + 1];
    const float* b_conv_b = (const float*)d_in[bi + 2];
    const float* b_xproj  = (const float*)d_in[bi + 3];
    const float* b_dt_w   = (const float*)d_in[bi + 4];
    const float* b_dt_b   = (const float*)d_in[bi + 5];
    const float* b_A_log  = (const float*)d_in[bi + 6];
    const float* b_D      = (const float*)d_in[bi + 7];
    const float* b_out_w  = (const float*)d_in[bi + 8];
    const float* fusion_w = (const float*)d_in[i_fw];
    const float* fusion_b = (const float*)d_in[i_fb];
    const float* ln_g     = (const float*)d_in[i_lg];
    const float* ln_b     = (const float*)d_in[i_lb];
    float* out = (float*)d_out;

    float* xdbl   = symaddr<float>(g_xdbl);
    float* delta  = symaddr<float>(g_delta);
    float* rbuf   = symaddr<float>(g_r);
    float* xpart  = symaddr<float>(g_xpart);
    float* aval   = symaddr<float>(g_Aval);
    __nv_bfloat16* xz    = symaddr<__nv_bfloat16>(g_xz);
    __nv_bfloat16* xhi   = symaddr<__nv_bfloat16>(g_xhi);
    __nv_bfloat16* wihi  = symaddr<__nv_bfloat16>(g_wihi);
    __nv_bfloat16* wohi  = symaddr<__nv_bfloat16>(g_wohi);
    __nv_bfloat16* fwhi  = symaddr<__nv_bfloat16>(g_fwhi);
    __nv_bfloat16* xpwhi = symaddr<__nv_bfloat16>(g_xpwhi);
    __nv_bfloat16* xpwlo = symaddr<__nv_bfloat16>(g_xpwlo);
    __nv_bfloat16* xihi  = symaddr<__nv_bfloat16>(g_xihi);
    __nv_bfloat16* yhi   = symaddr<__nv_bfloat16>(g_yhi);
    __nv_bfloat16* fuhi  = symaddr<__nv_bfloat16>(g_fuhi);

    const size_t XI_D = (size_t)MROWS * DINNER;
    const size_t XD_D = (size_t)MROWS * 64;

    // 0) fused prep: bf16 conversions + A' = -exp(A_log)*log2e
    PrepJobs J;
    const int nX  = MROWS * DMODEL / 4;
    const int nWI = WI_SZ / 4, nWO = WO_SZ / 4, nFW = FW_SZ / 4, nXP = XPW_SZ / 4;
    const int nAL = (DINNER * DSTATE) / 4;
    for (int k = 0; k < 10; k++) { J.lo[k] = nullptr; J.fo[k] = nullptr; }
    J.src[0] = (const float4*)x;        J.hi[0] = (ushort4*)xhi;
    J.src[1] = (const float4*)f_in_w;   J.hi[1] = (ushort4*)wihi;
    J.src[2] = (const float4*)b_in_w;   J.hi[2] = (ushort4*)(wihi + WI_SZ);
    J.src[3] = (const float4*)f_out_w;  J.hi[3] = (ushort4*)wohi;
    J.src[4] = (const float4*)b_out_w;  J.hi[4] = (ushort4*)(wohi + WO_SZ);
    J.src[5] = (const float4*)fusion_w; J.hi[5] = (ushort4*)fwhi;
    J.src[6] = (const float4*)f_xproj;  J.hi[6] = (ushort4*)xpwhi;            J.lo[6] = (ushort4*)xpwlo;
    J.src[7] = (const float4*)b_xproj;  J.hi[7] = (ushort4*)(xpwhi + XPW_SZ); J.lo[7] = (ushort4*)(xpwlo + XPW_SZ);
    J.src[8] = (const float4*)f_A_log;  J.hi[8] = nullptr; J.fo[8] = (float4*)aval;
    J.src[9] = (const float4*)b_A_log;  J.hi[9] = nullptr; J.fo[9] = (float4*)(aval + DINNER * DSTATE);
    int e = 0;
    e += nX;  J.end4[0] = e;
    e += nWI; J.end4[1] = e;
    e += nWI; J.end4[2] = e;
    e += nWO; J.end4[3] = e;
    e += nWO; J.end4[4] = e;
    e += nFW; J.end4[5] = e;
    e += nXP; J.end4[6] = e;
    e += nXP; J.end4[7] = e;
    e += nAL; J.end4[8] = e;
    e += nAL; J.end4[9] = e;
    prep_all_kernel<<<(e + 255) / 256, 256>>>(J);

    // 1) in_proj (HMMA 1-pass, double-buffered): xz[dir] = x(_flip) @ in_w^T
    mma_gemm<true, false, 1, false, 1><<<dim3(32, 16, 2), 128>>>(
        xhi, wihi, nullptr, wihi + WI_SZ, nullptr,
        nullptr, xz, 0, (size_t)MROWS * 2 * DINNER, 0,
        DMODEL, DMODEL, DMODEL, 2 * DINNER);

    // 2) causal depthwise conv + SiLU -> xihi
    conv_silu_kernel<<<dim3(128, 4), 256>>>(f_conv_w, f_conv_b, b_conv_w, b_conv_b);

    // 3) xproj (HMMA 2-pass B-split, double-buffered, split-K4)
    mma_gemm<false, false, 0, true, XKS><<<dim3(1, 16, 2 * XKS), 128>>>(
        xihi, xpwhi, xpwlo, xpwhi + XPW_SZ, xpwlo + XPW_SZ,
        xpart, nullptr, XI_D, (size_t)XKS * MROWS * 64, (size_t)MROWS * 64,
        DINNER, DINNER, DINNER, 64);
    xdbl_reduce_kernel<<<(2 * MROWS * 64) / 256, 256>>>();

    // 4) dtproj (SIMT): delta = softplus(dt @ dt_w^T + dt_b)
    gemm_nt<64, 64, 16, 4, 4, true>
        <<<dim3(16, 32, 2), 256>>>(xdbl, f_dt_w, b_dt_w, delta, f_dt_b, b_dt_b,
                                   XD_D, XI_D, MROWS, DINNER, DTRANK, 64, DTRANK, DINNER);

    // 5) chunked selective scan (+ fused gating, emits yhi)
    scanA_kernel<<<dim3(32, CH, 4), 128>>>();
    scanB_kernel<<<128, 128>>>();
    scanC_kernel<<<dim3(32, CH, 4), 128>>>(f_D, b_D);

    // 6) out_proj (HMMA 1-pass, double-buffered): fusein = y @ out_w^T
    mma_gemm<false, true, 1, false, 1><<<dim3(8, 16, 2), 128>>>(
        yhi, wohi, nullptr, wohi + WO_SZ, nullptr,
        nullptr, fuhi, XI_D, (size_t)DMODEL, 0,
        DINNER, DINNER, DINNER, 2 * DMODEL);

    // 7) fusion (HMMA 1-pass, double-buffered): r = fused @ fusion_w^T
    mma_gemm<false, false, 0, false, 1><<<dim3(8, 16, 1), 128>>>(
        fuhi, fwhi, nullptr, fwhi, nullptr,
        rbuf, nullptr, 0, 0, 0,
        2 * DMODEL, 2 * DMODEL, 2 * DMODEL, DMODEL);

    // 8) residual + bias + layernorm -> d_out
    ln_kernel<<<MROWS, 256>>>(x, fusion_b, ln_g, ln_b, out);

    (void)n_in; (void)out_size;
}

// round 16
// speedup vs baseline: 1.0631x; 1.0183x over previous
#include <cuda_runtime.h>
#include <cuda_bf16.h>
#include <cstdint>
#include <cstddef>

// ---------------------------------------------------------------------------
// BidirectionalMambaBlock — HMMA bf16 GEMMs (double-buffered 1-pass big /
// 2-pass xproj splitK4) + chunked scan   [R13 base + conv preload]
// ---------------------------------------------------------------------------

#define L_SEQ   1024
#define BATCH   2
#define DMODEL  512
#define DINNER  1024
#define DSTATE  16
#define DTRANK  32
#define MROWS   (BATCH * L_SEQ)     // 2048
#define CH      8
#define TC      (L_SEQ / CH)        // 128
#define XKS     4                   // split-K for xproj (HMMA)

#define WI_SZ   (2 * DINNER * DMODEL)
#define WO_SZ   (DMODEL * DINNER)
#define FW_SZ   (DMODEL * 2 * DMODEL)
#define XPW_SZ  (64 * DINNER)

// ------------------------- scratch (device globals) ------------------------
__device__ float g_xdbl[(size_t)2 * MROWS * 64];
__device__ float g_xpart[(size_t)2 * XKS * MROWS * 64];
__device__ float g_delta[(size_t)2 * MROWS * DINNER];
__device__ float g_r[(size_t)MROWS * DMODEL];
__device__ float g_Aval[2 * DINNER * DSTATE];
__device__ float g_hpart[(size_t)4 * CH * DINNER * DSTATE];
__device__ float g_hin[(size_t)4 * CH * DINNER * DSTATE];
__device__ float g_sumd[(size_t)4 * CH * DINNER];

// bf16 operands / intermediates (16B-aligned)
__device__ __align__(128) __nv_bfloat16 g_xz[(size_t)2 * MROWS * 2 * DINNER];
__device__ __align__(128) __nv_bfloat16 g_xhi[(size_t)MROWS * DMODEL];
__device__ __align__(128) __nv_bfloat16 g_wihi[(size_t)2 * WI_SZ];
__device__ __align__(128) __nv_bfloat16 g_wohi[(size_t)2 * WO_SZ];
__device__ __align__(128) __nv_bfloat16 g_fwhi[(size_t)FW_SZ];
__device__ __align__(128) __nv_bfloat16 g_xpwhi[(size_t)2 * XPW_SZ];
__device__ __align__(128) __nv_bfloat16 g_xpwlo[(size_t)2 * XPW_SZ];
__device__ __align__(128) __nv_bfloat16 g_xihi[(size_t)2 * MROWS * DINNER];
__device__ __align__(128) __nv_bfloat16 g_yhi[(size_t)2 * MROWS * DINNER];
__device__ __align__(128) __nv_bfloat16 g_fuhi[(size_t)MROWS * 2 * DMODEL];

// ------------------------------ device helpers -----------------------------
__device__ __forceinline__ float2 ffma2(float2 a, float2 b, float2 c) {
    unsigned long long ua = *reinterpret_cast<unsigned long long*>(&a);
    unsigned long long ub = *reinterpret_cast<unsigned long long*>(&b);
    unsigned long long uc = *reinterpret_cast<unsigned long long*>(&c);
    unsigned long long ud;
    asm("fma.rn.f32x2 %0, %1, %2, %3;" : "=l"(ud) : "l"(ua), "l"(ub), "l"(uc));
    return *reinterpret_cast<float2*>(&ud);
}
__device__ __forceinline__ float ex2f(float x) {
    float y; asm("ex2.approx.ftz.f32 %0, %1;" : "=f"(y) : "f"(x)); return y;
}
__device__ __forceinline__ float softplusf(float x) {
    return (x > 15.0f) ? x : __logf(1.0f + __expf(x));
}
__device__ __forceinline__ float siluf(float x) {
    return __fdividef(x, 1.0f + __expf(-x));
}
__device__ __forceinline__ uint32_t smem_u32(const void* p) {
    uint32_t a;
    asm("{ .reg .u64 t; cvta.to.shared.u64 t, %1; cvt.u32.u64 %0, t; }" : "=r"(a) : "l"(p));
    return a;
}
__device__ __forceinline__ void ldsm4(uint32_t* r, uint32_t addr) {
    asm volatile("ldmatrix.sync.aligned.m8n8.x4.shared.b16 {%0,%1,%2,%3}, [%4];"
                 : "=r"(r[0]), "=r"(r[1]), "=r"(r[2]), "=r"(r[3]) : "r"(addr));
}
__device__ __forceinline__ void mma_bf16(float* c, const uint32_t* a, const uint32_t* b) {
    asm volatile(
        "mma.sync.aligned.m16n8k16.row.col.f32.bf16.bf16.f32 "
        "{%0,%1,%2,%3}, {%4,%5,%6,%7}, {%8,%9}, {%0,%1,%2,%3};"
        : "+f"(c[0]), "+f"(c[1]), "+f"(c[2]), "+f"(c[3])
        : "r"(a[0]), "r"(a[1]), "r"(a[2]), "r"(a[3]), "r"(b[0]), "r"(b[1]));
}
__device__ __forceinline__ unsigned short bits(__nv_bfloat16 v) {
    return *reinterpret_cast<unsigned short*>(&v);
}
__device__ __forceinline__ float bf2f(__nv_bfloat16 v) { return __bfloat162float(v); }
__device__ __forceinline__ float4 ld4bf(const __nv_bfloat16* p) {
    ushort4 u = *reinterpret_cast<const ushort4*>(p);
    float4 f;
    f.x = bf2f(*reinterpret_cast<__nv_bfloat16*>(&u.x));
    f.y = bf2f(*reinterpret_cast<__nv_bfloat16*>(&u.y));
    f.z = bf2f(*reinterpret_cast<__nv_bfloat16*>(&u.z));
    f.w = bf2f(*reinterpret_cast<__nv_bfloat16*>(&u.w));
    return f;
}

// ------------- fused prep: bf16 hi(/lo) conversions + A' segments -----------
struct PrepJobs {
    const float4* src[10];
    ushort4* hi[10];
    ushort4* lo[10];   // nullptr -> no lo plane
    float4* fo[10];    // non-null -> A' mode: out = -exp(v)*log2e (fp32)
    int end4[10];
};

__global__ void prep_all_kernel(PrepJobs J)
{
    const int i = blockIdx.x * 256 + threadIdx.x;
    if (i >= J.end4[9]) return;
    int s = 0;
#pragma unroll
    for (int k = 0; k < 9; k++) s += (i >= J.end4[k]) ? 1 : 0;
    const int base = s ? J.end4[s - 1] : 0;
    const int off = i - base;

    const float4 v = J.src[s][off];
    if (J.fo[s]) {
        float4 o;
        o.x = -__expf(v.x) * 1.4426950408889634f;
        o.y = -__expf(v.y) * 1.4426950408889634f;
        o.z = -__expf(v.z) * 1.4426950408889634f;
        o.w = -__expf(v.w) * 1.4426950408889634f;
        J.fo[s][off] = o;
        return;
    }
    __nv_bfloat16 h0 = __float2bfloat16(v.x), h1 = __float2bfloat16(v.y);
    __nv_bfloat16 h2 = __float2bfloat16(v.z), h3 = __float2bfloat16(v.w);
    ushort4 uh; uh.x = bits(h0); uh.y = bits(h1); uh.z = bits(h2); uh.w = bits(h3);
    J.hi[s][off] = uh;
    if (J.lo[s]) {
        ushort4 ul;
        ul.x = bits(__float2bfloat16(v.x - bf2f(h0)));
        ul.y = bits(__float2bfloat16(v.y - bf2f(h1)));
        ul.z = bits(__float2bfloat16(v.z - bf2f(h2)));
        ul.w = bits(__float2bfloat16(v.w - bf2f(h3)));
        J.lo[s][off] = ul;
    }
}

// -------------------- HMMA bf16 GEMM (NT), dir-batched ----------------------
// FAST (!BSPLIT): 1-pass, double-buffered smem, 1 sync/chunk.
// BSPLIT: 2-pass B hi/lo (A hi only), single-buffered (xproj).
// CTA tile 128x64, BK=32, 4 warps. blockIdx.z = dir*KS + ks.
// OUTMODE 0: fp32 C; 1: bf16 hi C.
template<bool FLIPA, bool FLIPSTORE, int OUTMODE, bool BSPLIT, int KS>
__global__ void __launch_bounds__(128)
mma_gemm(const __nv_bfloat16* __restrict__ Ahi,
         const __nv_bfloat16* __restrict__ Bhi0, const __nv_bfloat16* __restrict__ Blo0,
         const __nv_bfloat16* __restrict__ Bhi1, const __nv_bfloat16* __restrict__ Blo1,
         float* __restrict__ Cf, __nv_bfloat16* __restrict__ Chi,
         size_t aStride, size_t cStride, size_t sliceStride,
         int K, int lda, int ldb, int ldc)
{
    __shared__ __align__(16) __nv_bfloat16 sA[2][128][40];
    __shared__ __align__(16) __nv_bfloat16 sB[2][64][40];

    const int tid = threadIdx.x;
    const int warp = tid >> 5, lane = tid & 31;
    const int wm = warp >> 1, wn = warp & 1;
    const int z = blockIdx.z;
    const int dir = z / KS, ks = z % KS;
    const int bm = blockIdx.y * 128, bn = blockIdx.x * 64;

    const __nv_bfloat16* __restrict__ Bh = dir ? Bhi1 : Bhi0;
    const __nv_bfloat16* __restrict__ Bl = dir ? Blo1 : Blo0;
    Ahi += (size_t)dir * aStride;

    const int kBase = ks * (K / KS);
    const int nCh = (K / KS) >> 5;

    float acc[4][4][4];
#pragma unroll
    for (int i = 0; i < 4; i++)
#pragma unroll
        for (int j = 0; j < 4; j++)
#pragma unroll
            for (int e = 0; e < 4; e++) acc[i][j][e] = 0.0f;

    const int arow = wm * 64 + (lane & 15);
    const int acol = (lane >> 4) << 3;
    const int brow = wn * 32 + ((lane >> 4) << 3) + (lane & 7);
    const int bcol = ((lane >> 3) & 1) << 3;

    const uint32_t sa0 = smem_u32(&sA[0][0][0]);
    const uint32_t sa1 = smem_u32(&sA[1][0][0]);
    const uint32_t sb0 = smem_u32(&sB[0][0][0]);
    const uint32_t sb1 = smem_u32(&sB[1][0][0]);

    if (!BSPLIT) {
        uint4 ra[4], rb[2];
#pragma unroll
        for (int i = 0; i < 4; i++) {
            const int idx = i * 128 + tid, row = idx >> 2, q = idx & 3;
            int gr = bm + row; if (FLIPA && dir) gr ^= (L_SEQ - 1);
            ra[i] = *reinterpret_cast<const uint4*>(Ahi + (size_t)gr * lda + kBase + q * 8);
        }
#pragma unroll
        for (int i = 0; i < 2; i++) {
            const int idx = i * 128 + tid, row = idx >> 2, q = idx & 3;
            rb[i] = *reinterpret_cast<const uint4*>(Bh + (size_t)(bn + row) * ldb + kBase + q * 8);
        }
#pragma unroll
        for (int i = 0; i < 4; i++) {
            const int idx = i * 128 + tid, row = idx >> 2, q = idx & 3;
            *reinterpret_cast<uint4*>(&sA[0][row][q * 8]) = ra[i];
        }
#pragma unroll
        for (int i = 0; i < 2; i++) {
            const int idx = i * 128 + tid, row = idx >> 2, q = idx & 3;
            *reinterpret_cast<uint4*>(&sB[0][row][q * 8]) = rb[i];
        }
        if (nCh > 1) {
            const int k0 = kBase + 32;
#pragma unroll
            for (int i = 0; i < 4; i++) {
                const int idx = i * 128 + tid, row = idx >> 2, q = idx & 3;
                int gr = bm + row; if (FLIPA && dir) gr ^= (L_SEQ - 1);
                ra[i] = *reinterpret_cast<const uint4*>(Ahi + (size_t)gr * lda + k0 + q * 8);
            }
#pragma unroll
            for (int i = 0; i < 2; i++) {
                const int idx = i * 128 + tid, row = idx >> 2, q = idx & 3;
                rb[i] = *reinterpret_cast<const uint4*>(Bh + (size_t)(bn + row) * ldb + k0 + q * 8);
            }
        }
        __syncthreads();

        for (int ch = 0; ch < nCh; ++ch) {
            const int cur = ch & 1, nxt = cur ^ 1;
            if (ch + 1 < nCh) {
#pragma unroll
                for (int i = 0; i < 4; i++) {
                    const int idx = i * 128 + tid, row = idx >> 2, q = idx & 3;
                    *reinterpret_cast<uint4*>(&sA[nxt][row][q * 8]) = ra[i];
                }
#pragma unroll
                for (int i = 0; i < 2; i++) {
                    const int idx = i * 128 + tid, row = idx >> 2, q = idx & 3;
                    *reinterpret_cast<uint4*>(&sB[nxt][row][q * 8]) = rb[i];
                }
                if (ch + 2 < nCh) {
                    const int k0 = kBase + ((ch + 2) << 5);
#pragma unroll
                    for (int i = 0; i < 4; i++) {
                        const int idx = i * 128 + tid, row = idx >> 2, q = idx & 3;
                        int gr = bm + row; if (FLIPA && dir) gr ^= (L_SEQ - 1);
                        ra[i] = *reinterpret_cast<const uint4*>(Ahi + (size_t)gr * lda + k0 + q * 8);
                    }
#pragma unroll
                    for (int i = 0; i < 2; i++) {
                        const int idx = i * 128 + tid, row = idx >> 2, q = idx & 3;
                        rb[i] = *reinterpret_cast<const uint4*>(Bh + (size_t)(bn + row) * ldb + k0 + q * 8);
                    }
                }
            }
            const uint32_t sa = cur ? sa1 : sa0;
            const uint32_t sb = cur ? sb1 : sb0;
#pragma unroll
            for (int k16 = 0; k16 < 32; k16 += 16) {
                uint32_t ah[4][4], bh[2][4];
#pragma unroll
                for (int mi = 0; mi < 4; mi++)
                    ldsm4(ah[mi], sa + ((uint32_t)(arow + mi * 16) * 40 + k16 + acol) * 2);
#pragma unroll
                for (int p = 0; p < 2; p++)
                    ldsm4(bh[p], sb + ((uint32_t)(brow + p * 16) * 40 + k16 + bcol) * 2);
#pragma unroll
                for (int mi = 0; mi < 4; mi++)
#pragma unroll
                    for (int nj = 0; nj < 4; nj++)
                        mma_bf16(acc[mi][nj], ah[mi], &bh[nj >> 1][(nj & 1) * 2]);
            }
            __syncthreads();
        }
    } else {
        uint4 ra[4], rb[2][2];
#pragma unroll
        for (int i = 0; i < 4; i++) {
            const int idx = i * 128 + tid, row = idx >> 2, q = idx & 3;
            int gr = bm + row; if (FLIPA && dir) gr ^= (L_SEQ - 1);
            ra[i] = *reinterpret_cast<const uint4*>(Ahi + (size_t)gr * lda + kBase + q * 8);
        }
#pragma unroll
        for (int i = 0; i < 2; i++) {
            const int idx = i * 128 + tid, row = idx >> 2, q = idx & 3;
            const size_t off = (size_t)(bn + row) * ldb + kBase + q * 8;
            rb[0][i] = *reinterpret_cast<const uint4*>(Bh + off);
            rb[1][i] = *reinterpret_cast<const uint4*>(Bl + off);
        }

        for (int ch = 0; ch < nCh; ++ch) {
#pragma unroll
            for (int i = 0; i < 4; i++) {
                const int idx = i * 128 + tid, row = idx >> 2, q = idx & 3;
                *reinterpret_cast<uint4*>(&sA[0][row][q * 8]) = ra[i];
            }
#pragma unroll
            for (int i = 0; i < 2; i++) {
                const int idx = i * 128 + tid, row = idx >> 2, q = idx & 3;
                *reinterpret_cast<uint4*>(&sB[0][row][q * 8]) = rb[0][i];
                *reinterpret_cast<uint4*>(&sB[1][row][q * 8]) = rb[1][i];
            }
            __syncthreads();

            if (ch + 1 < nCh) {
                const int k0 = kBase + ((ch + 1) << 5);
#pragma unroll
                for (int i = 0; i < 4; i++) {
                    const int idx = i * 128 + tid, row = idx >> 2, q = idx & 3;
                    int gr = bm + row; if (FLIPA && dir) gr ^= (L_SEQ - 1);
                    ra[i] = *reinterpret_cast<const uint4*>(Ahi + (size_t)gr * lda + k0 + q * 8);
                }
#pragma unroll
                for (int i = 0; i < 2; i++) {
                    const int idx = i * 128 + tid, row = idx >> 2, q = idx & 3;
                    const size_t off = (size_t)(bn + row) * ldb + k0 + q * 8;
                    rb[0][i] = *reinterpret_cast<const uint4*>(Bh + off);
                    rb[1][i] = *reinterpret_cast<const uint4*>(Bl + off);
                }
            }

#pragma unroll
            for (int k16 = 0; k16 < 32; k16 += 16) {
                uint32_t ah[4][4], bh[2][4], bl[2][4];
#pragma unroll
                for (int mi = 0; mi < 4; mi++)
                    ldsm4(ah[mi], sa0 + ((uint32_t)(arow + mi * 16) * 40 + k16 + acol) * 2);
#pragma unroll
                for (int p = 0; p < 2; p++) {
                    const uint32_t off = ((uint32_t)(brow + p * 16) * 40 + k16 + bcol) * 2;
                    ldsm4(bh[p], sb0 + off);
                    ldsm4(bl[p], sb1 + off);
                }
#pragma unroll
                for (int mi = 0; mi < 4; mi++)
#pragma unroll
                    for (int nj = 0; nj < 4; nj++) {
                        mma_bf16(acc[mi][nj], ah[mi], &bh[nj >> 1][(nj & 1) * 2]);
                        mma_bf16(acc[mi][nj], ah[mi], &bl[nj >> 1][(nj & 1) * 2]);
                    }
            }
            __syncthreads();
        }
    }

    // epilogue
    if (OUTMODE == 0) Cf += (size_t)dir * cStride + (size_t)ks * sliceStride;
    else Chi += (size_t)dir * cStride;

#pragma unroll
    for (int mi = 0; mi < 4; mi++) {
#pragma unroll
        for (int nj = 0; nj < 4; nj++) {
            const int col = bn + wn * 32 + nj * 8 + (lane & 3) * 2;
            int r0 = bm + wm * 64 + mi * 16 + (lane >> 2);
            int r1 = r0 + 8;
            if (FLIPSTORE && dir) { r0 ^= (L_SEQ - 1); r1 ^= (L_SEQ - 1); }
            const float* a = acc[mi][nj];
            if (OUTMODE == 0) {
                *reinterpret_cast<float2*>(Cf + (size_t)r0 * ldc + col) = make_float2(a[0], a[1]);
                *reinterpret_cast<float2*>(Cf + (size_t)r1 * ldc + col) = make_float2(a[2], a[3]);
            } else {
                ushort2 u0, u1;
                u0.x = bits(__float2bfloat16(a[0]));
                u0.y = bits(__float2bfloat16(a[1]));
                u1.x = bits(__float2bfloat16(a[2]));
                u1.y = bits(__float2bfloat16(a[3]));
                *reinterpret_cast<ushort2*>(Chi + (size_t)r0 * ldc + col) = u0;
                *reinterpret_cast<ushort2*>(Chi + (size_t)r1 * ldc + col) = u1;
            }
        }
    }
}

// ---------------- pipelined SIMT SGEMM (NT) — dtproj only -------------------
template<int BM, int BN, int BK, int TM, int TN, bool SOFTPLUS>
__global__ void __launch_bounds__((BM / TM) * (BN / TN))
gemm_nt(const float* __restrict__ A, const float* __restrict__ B0,
        const float* __restrict__ B1, float* __restrict__ C,
        const float* __restrict__ bias0, const float* __restrict__ bias1,
        size_t aStride, size_t cStride,
        int M, int N, int K, int lda, int ldb, int ldc)
{
    constexpr int NTHR = (BM / TM) * (BN / TN);
    constexpr int TX = BN / TN;
    constexpr int PAD = 4;
    constexpr int AKT = BK / 4;
    constexpr int ALD = (BM * BK) / (NTHR * 4);
    constexpr int BLD = (BN * BK) / (NTHR * 4);
    constexpr int ARS = NTHR / AKT;

    __shared__ __align__(16) float As[2][BK][BM + PAD];
    __shared__ __align__(16) float Bs[2][BK][BN + PAD];

    const int dir = blockIdx.z;
    const float* __restrict__ Bw = dir ? B1 : B0;
    const float* __restrict__ bias = dir ? bias1 : bias0;
    A += (size_t)dir * aStride;
    C += (size_t)dir * cStride;

    const int tid = threadIdx.x;
    const int bn = blockIdx.x * BN;
    const int bm = blockIdx.y * BM;
    const int tx = tid % TX;
    const int ty = tid / TX;
    const int ar = tid / AKT;
    const int ac = (tid % AKT) * 4;

    const int nIter = K / BK;

    float2 acc[TM][TN / 2];
#pragma unroll
    for (int i = 0; i < TM; i++)
#pragma unroll
        for (int j = 0; j < TN / 2; j++) acc[i][j] = make_float2(0.0f, 0.0f);

    float4 ra[ALD], rb[BLD];

#pragma unroll
    for (int i = 0; i < ALD; i++)
        ra[i] = *reinterpret_cast<const float4*>(A + (size_t)(bm + ar + i * ARS) * lda + ac);
#pragma unroll
    for (int i = 0; i < BLD; i++)
        rb[i] = *reinterpret_cast<const float4*>(Bw + (size_t)(bn + ar + i * ARS) * ldb + ac);

#pragma unroll
    for (int i = 0; i < ALD; i++) {
        int r = ar + i * ARS;
        As[0][ac + 0][r] = ra[i].x; As[0][ac + 1][r] = ra[i].y;
        As[0][ac + 2][r] = ra[i].z; As[0][ac + 3][r] = ra[i].w;
    }
#pragma unroll
    for (int i = 0; i < BLD; i++) {
        int r = ar + i * ARS;
        Bs[0][ac + 0][r] = rb[i].x; Bs[0][ac + 1][r] = rb[i].y;
        Bs[0][ac + 2][r] = rb[i].z; Bs[0][ac + 3][r] = rb[i].w;
    }
    __syncthreads();

    for (int it = 0; it < nIter; ++it) {
        const int cur = it & 1;
        const bool more = (it + 1 < nIter);
        if (more) {
            const int kg = (it + 1) * BK;
#pragma unroll
            for (int i = 0; i < ALD; i++)
                ra[i] = *reinterpret_cast<const float4*>(A + (size_t)(bm + ar + i * ARS) * lda + kg + ac);
#pragma unroll
            for (int i = 0; i < BLD; i++)
                rb[i] = *reinterpret_cast<const float4*>(Bw + (size_t)(bn + ar + i * ARS) * ldb + kg + ac);
        }

#pragma unroll
        for (int k = 0; k < BK; k++) {
            float a[TM];
            float2 b2[TN / 2];
#pragma unroll
            for (int i = 0; i < TM; i += 4) {
                float4 t = *reinterpret_cast<const float4*>(&As[cur][k][ty * TM + i]);
                a[i] = t.x; a[i + 1] = t.y; a[i + 2] = t.z; a[i + 3] = t.w;
            }
#pragma unroll
            for (int j = 0; j < TN; j += 4) {
                float4 t = *reinterpret_cast<const float4*>(&Bs[cur][k][tx * TN + j]);
                b2[j / 2]     = make_float2(t.x, t.y);
                b2[j / 2 + 1] = make_float2(t.z, t.w);
            }
#pragma unroll
            for (int i = 0; i < TM; i++) {
                float2 a2 = make_float2(a[i], a[i]);
#pragma unroll
                for (int j = 0; j < TN / 2; j++)
                    acc[i][j] = ffma2(a2, b2[j], acc[i][j]);
            }
        }

        if (more) {
            const int nxt = cur ^ 1;
#pragma unroll
            for (int i = 0; i < ALD; i++) {
                int r = ar + i * ARS;
                As[nxt][ac + 0][r] = ra[i].x; As[nxt][ac + 1][r] = ra[i].y;
                As[nxt][ac + 2][r] = ra[i].z; As[nxt][ac + 3][r] = ra[i].w;
            }
#pragma unroll
            for (int i = 0; i < BLD; i++) {
                int r = ar + i * ARS;
                Bs[nxt][ac + 0][r] = rb[i].x; Bs[nxt][ac + 1][r] = rb[i].y;
                Bs[nxt][ac + 2][r] = rb[i].z; Bs[nxt][ac + 3][r] = rb[i].w;
            }
            __syncthreads();
        }
    }

#pragma unroll
    for (int i = 0; i < TM; i++) {
        int m = bm + ty * TM + i;
#pragma unroll
        for (int j = 0; j < TN / 2; j++) {
            int n = bn + tx * TN + 2 * j;
            float2 v = acc[i][j];
            if (SOFTPLUS) {
                v.x = softplusf(v.x + bias[n]);
                v.y = softplusf(v.y + bias[n + 1]);
            }
            *reinterpret_cast<float2*>(C + (size_t)m * ldc + n) = v;
        }
    }
}

// ----------------- split-K reduce for xproj partials ------------------------
__global__ void xdbl_reduce_kernel()
{
    const int idx = blockIdx.x * 256 + threadIdx.x;
    const size_t per = (size_t)MROWS * 64;
    const int dir = idx / (int)per;
    const size_t off = (size_t)idx - (size_t)dir * per;
    float s = 0.0f;
#pragma unroll
    for (int ks = 0; ks < XKS; ks++)
        s += g_xpart[((size_t)dir * XKS + ks) * per + off];
    g_xdbl[(size_t)dir * per + off] = s;
}

// -------- causal depthwise conv + SiLU (preloaded window) -> bf16 hi --------
__global__ void conv_silu_kernel(const float* __restrict__ cwf, const float* __restrict__ cbf,
                                 const float* __restrict__ cwb, const float* __restrict__ cbb)
{
    const int tb   = blockIdx.x;
    const int dirb = blockIdx.y;
    const int dir = dirb >> 1, b = dirb & 1;
    const int l0 = tb * 8;
    const int d0 = threadIdx.x * 4;
    const float* cw = dir ? cwb : cwf;
    const float* cb = dir ? cbb : cbf;

    float4 w0 = *reinterpret_cast<const float4*>(cw + (size_t)(d0 + 0) * 4);
    float4 w1 = *reinterpret_cast<const float4*>(cw + (size_t)(d0 + 1) * 4);
    float4 w2 = *reinterpret_cast<const float4*>(cw + (size_t)(d0 + 2) * 4);
    float4 w3 = *reinterpret_cast<const float4*>(cw + (size_t)(d0 + 3) * 4);
    const float4 bias = *reinterpret_cast<const float4*>(cb + d0);

    const size_t base = ((size_t)dir * MROWS + (size_t)b * L_SEQ) * (2 * DINNER) + d0;
    const float4 zero = make_float4(0.f, 0.f, 0.f, 0.f);

    // preload the full 11-row window (independent loads, MLP=11)
    float4 xw[11];
#pragma unroll
    for (int j = 0; j < 11; j++) {
        const int lr = l0 - 3 + j;
        xw[j] = (lr >= 0) ? ld4bf(g_xz + base + (size_t)lr * (2 * DINNER)) : zero;
    }

    const size_t obase = ((size_t)dir * MROWS + (size_t)b * L_SEQ + l0) * DINNER + d0;

#pragma unroll
    for (int i = 0; i < 8; i++) {
        const float4 xm3 = xw[i], xm2 = xw[i + 1], xm1 = xw[i + 2], xc = xw[i + 3];
        float4 acc = bias;
        acc.x = fmaf(w0.x, xm3.x, fmaf(w0.y, xm2.x, fmaf(w0.z, xm1.x, fmaf(w0.w, xc.x, acc.x))));
        acc.y = fmaf(w1.x, xm3.y, fmaf(w1.y, xm2.y, fmaf(w1.z, xm1.y, fmaf(w1.w, xc.y, acc.y))));
        acc.z = fmaf(w2.x, xm3.z, fmaf(w2.y, xm2.z, fmaf(w2.z, xm1.z, fmaf(w2.w, xc.z, acc.z))));
        acc.w = fmaf(w3.x, xm3.w, fmaf(w3.y, xm2.w, fmaf(w3.z, xm1.w, fmaf(w3.w, xc.w, acc.w))));
        float4 o;
        o.x = siluf(acc.x); o.y = siluf(acc.y);
        o.z = siluf(acc.z); o.w = siluf(acc.w);

        ushort4 uh;
        uh.x = bits(__float2bfloat16(o.x));
        uh.y = bits(__float2bfloat16(o.y));
        uh.z = bits(__float2bfloat16(o.z));
        uh.w = bits(__float2bfloat16(o.w));
        *reinterpret_cast<ushort4*>(g_xihi + obase + (size_t)i * DINNER) = uh;
    }
}

// ------------------------------ chunked selective scan ----------------------
__global__ void scanA_kernel()
{
    const int db  = blockIdx.z;
    const int dir = db >> 1, b = db & 1;
    const int c   = blockIdx.y;
    const int t   = threadIdx.x;
    const int g4  = t & 3;
    const int d   = blockIdx.x * 32 + (t >> 2);

    const size_t rb = ((size_t)dir * MROWS + (size_t)b * L_SEQ + (size_t)c * TC) * DINNER + d;
    const float* __restrict__ dp = g_delta + rb;
    const __nv_bfloat16* __restrict__ xp = g_xihi + rb;
    const size_t xb = ((size_t)dir * MROWS + (size_t)b * L_SEQ + (size_t)c * TC) * 64;
    const float4* __restrict__ Bp = reinterpret_cast<const float4*>(g_xdbl + xb + 32) + g4;

    const float* ap = g_Aval + ((size_t)dir * DINNER + d) * DSTATE + 4 * g4;
    const float a0 = ap[0], a1 = ap[1], a2 = ap[2], a3 = ap[3];

    float h0 = 0.f, h1 = 0.f, h2 = 0.f, h3 = 0.f, sd = 0.f;

    for (int l = 0; l < TC; l++) {
        const float dlt = dp[(size_t)l * DINNER];
        const float xiv = bf2f(xp[(size_t)l * DINNER]);
        const float4 Bv = Bp[l * 16];
        const float u = dlt * xiv;
        h0 = fmaf(ex2f(dlt * a0), h0, u * Bv.x);
        h1 = fmaf(ex2f(dlt * a1), h1, u * Bv.y);
        h2 = fmaf(ex2f(dlt * a2), h2, u * Bv.z);
        h3 = fmaf(ex2f(dlt * a3), h3, u * Bv.w);
        sd += dlt;
    }
    const size_t hi = (((size_t)db * CH + c) * DINNER + d) * DSTATE + 4 * g4;
    float4 hv; hv.x = h0; hv.y = h1; hv.z = h2; hv.w = h3;
    *reinterpret_cast<float4*>(g_hpart + hi) = hv;
    if (g4 == 0) g_sumd[((size_t)db * CH + c) * DINNER + d] = sd;
}

__global__ void scanB_kernel()
{
    const int idx = blockIdx.x * 128 + threadIdx.x;
    const int g4 = idx & 3;
    const int d  = (idx >> 2) & (DINNER - 1);
    const int db = idx >> 12;
    const int dir = db >> 1;

    const float* ap = g_Aval + ((size_t)dir * DINNER + d) * DSTATE + 4 * g4;
    const float a0 = ap[0], a1 = ap[1], a2 = ap[2], a3 = ap[3];

    float h0 = 0.f, h1 = 0.f, h2 = 0.f, h3 = 0.f;
#pragma unroll
    for (int c = 0; c < CH; c++) {
        const size_t hi = (((size_t)db * CH + c) * DINNER + d) * DSTATE + 4 * g4;
        float4 hv; hv.x = h0; hv.y = h1; hv.z = h2; hv.w = h3;
        *reinterpret_cast<float4*>(g_hin + hi) = hv;
        const float S = g_sumd[((size_t)db * CH + c) * DINNER + d];
        const float4 hp = *reinterpret_cast<const float4*>(g_hpart + hi);
        h0 = fmaf(ex2f(S * a0), h0, hp.x);
        h1 = fmaf(ex2f(S * a1), h1, hp.y);
        h2 = fmaf(ex2f(S * a2), h2, hp.z);
        h3 = fmaf(ex2f(S * a3), h3, hp.w);
    }
}

__global__ void scanC_kernel(const float* __restrict__ Df, const float* __restrict__ Db)
{
    const int db  = blockIdx.z;
    const int dir = db >> 1, b = db & 1;
    const int c   = blockIdx.y;
    const int t   = threadIdx.x;
    const int g4  = t & 3;
    const int d   = blockIdx.x * 32 + (t >> 2);

    const size_t rb = ((size_t)dir * MROWS + (size_t)b * L_SEQ + (size_t)c * TC) * DINNER + d;
    const float* __restrict__ dp = g_delta + rb;
    const __nv_bfloat16* __restrict__ xp = g_xihi + rb;
    const size_t xb = ((size_t)dir * MROWS + (size_t)b * L_SEQ + (size_t)c * TC) * 64;
    const float4* __restrict__ Bp = reinterpret_cast<const float4*>(g_xdbl + xb + 32) + g4;
    const float4* __restrict__ Cp = reinterpret_cast<const float4*>(g_xdbl + xb + 48) + g4;
    const __nv_bfloat16* __restrict__ zp =
        g_xz + ((size_t)dir * MROWS + (size_t)b * L_SEQ + (size_t)c * TC) * (2 * DINNER) + DINNER + d;

    const float* ap = g_Aval + ((size_t)dir * DINNER + d) * DSTATE + 4 * g4;
    const float a0 = ap[0], a1 = ap[1], a2 = ap[2], a3 = ap[3];
    const float Dv = (dir ? Db : Df)[d];

    const size_t hi = (((size_t)db * CH + c) * DINNER + d) * DSTATE + 4 * g4;
    const float4 hin = *reinterpret_cast<const float4*>(g_hin + hi);
    float h0 = hin.x, h1 = hin.y, h2 = hin.z, h3 = hin.w;

    for (int l = 0; l < TC; l++) {
        const float dlt = dp[(size_t)l * DINNER];
        const float xiv = bf2f(xp[(size_t)l * DINNER]);
        const float4 Bv = Bp[l * 16];
        const float4 Cv = Cp[l * 16];
        const float u = dlt * xiv;
        h0 = fmaf(ex2f(dlt * a0), h0, u * Bv.x);
        h1 = fmaf(ex2f(dlt * a1), h1, u * Bv.y);
        h2 = fmaf(ex2f(dlt * a2), h2, u * Bv.z);
        h3 = fmaf(ex2f(dlt * a3), h3, u * Bv.w);
        float y = fmaf(h0, Cv.x, h1 * Cv.y) + fmaf(h2, Cv.z, h3 * Cv.w);
        y += __shfl_xor_sync(0xffffffffu, y, 1);
        y += __shfl_xor_sync(0xffffffffu, y, 2);
        if (g4 == 0) {
            const float z = bf2f(zp[(size_t)l * 2 * DINNER]);
            const float yv = fmaf(xiv, Dv, y) * siluf(z);
            g_yhi[rb + (size_t)l * DINNER] = __float2bfloat16(yv);
        }
    }
}

// ---------------- residual + fusion bias + LayerNorm ------------------------
__global__ void ln_kernel(const float* __restrict__ x, const float* __restrict__ fb,
                          const float* __restrict__ lg, const float* __restrict__ lb,
                          float* __restrict__ out)
{
    const int m = blockIdx.x;
    const int t = threadIdx.x;
    const float* rr = g_r + (size_t)m * DMODEL;
    const float* xr = x + (size_t)m * DMODEL;

    float v0 = xr[t]       + rr[t]       + fb[t];
    float v1 = xr[t + 256] + rr[t + 256] + fb[t + 256];
    float s = v0 + v1;
    float q = v0 * v0 + v1 * v1;
#pragma unroll
    for (int o = 16; o > 0; o >>= 1) {
        s += __shfl_xor_sync(0xffffffffu, s, o);
        q += __shfl_xor_sync(0xffffffffu, q, o);
    }
    __shared__ float ss[8], qs[8];
    __shared__ float mu_s, inv_s;
    if ((t & 31) == 0) { ss[t >> 5] = s; qs[t >> 5] = q; }
    __syncthreads();
    if (t == 0) {
        float S = 0.f, Q = 0.f;
#pragma unroll
        for (int i = 0; i < 8; i++) { S += ss[i]; Q += qs[i]; }
        float mu = S * (1.0f / DMODEL);
        float var = Q * (1.0f / DMODEL) - mu * mu;
        mu_s = mu;
        inv_s = rsqrtf(var + 1e-5f);
    }
    __syncthreads();
    const float mu = mu_s, inv = inv_s;
    out[(size_t)m * DMODEL + t]       = (v0 - mu) * inv * lg[t]       + lb[t];
    out[(size_t)m * DMODEL + t + 256] = (v1 - mu) * inv * lg[t + 256] + lb[t + 256];
}

// ------------------------------ host launcher -------------------------------
template<typename T>
static T* symaddr(const void* sym) {
    void* p = nullptr;
    cudaGetSymbolAddress(&p, sym);
    return reinterpret_cast<T*>(p);
}

extern "C" void kernel_launch(void* const* d_in, const int* in_sizes, int n_in,
                              void* d_out, int out_size)
{
    // Resolve input ordering: f_in_w = 1048576, fusion_w = 524288
    int fi, bi, i_fw, i_fb, i_lg, i_lb;
    if (in_sizes[1] == 2048 * 512) {          // signature order
        fi = 1; bi = 10; i_fw = 19; i_fb = 20; i_lg = 21; i_lb = 22;
    } else {                                  // dict order
        i_fw = 1; i_fb = 2; i_lg = 3; i_lb = 4; fi = 5; bi = 14;
    }

    const float* x        = (const float*)d_in[0];
    const float* f_in_w   = (const float*)d_in[fi + 0];
    const float* f_conv_w = (const float*)d_in[fi + 1];
    const float* f_conv_b = (const float*)d_in[fi + 2];
    const float* f_xproj  = (const float*)d_in[fi + 3];
    const float* f_dt_w   = (const float*)d_in[fi + 4];
    const float* f_dt_b   = (const float*)d_in[fi + 5];
    const float* f_A_log  = (const float*)d_in[fi + 6];
    const float* f_D      = (const float*)d_in[fi + 7];
    const float* f_out_w  = (const float*)d_in[fi + 8];
    const float* b_in_w   = (const float*)d_in[bi + 0];
    const float* b_conv_w = (const float*)d_in[bi + 1];
    const float* b_conv_b = (const float*)d_in[bi + 2];
    const float* b_xproj  = (const float*)d_in[bi + 3];
    const float* b_dt_w   = (const float*)d_in[bi + 4];
    const float* b_dt_b   = (const float*)d_in[bi + 5];
    const float* b_A_log  = (const float*)d_in[bi + 6];
    const float* b_D      = (const float*)d_in[bi + 7];
    const float* b_out_w  = (const float*)d_in[bi + 8];
    const float* fusion_w = (const float*)d_in[i_fw];
    const float* fusion_b = (const float*)d_in[i_fb];
    const float* ln_g     = (const float*)d_in[i_lg];
    const float* ln_b     = (const float*)d_in[i_lb];
    float* out = (float*)d_out;

    float* xdbl   = symaddr<float>(g_xdbl);
    float* delta  = symaddr<float>(g_delta);
    float* rbuf   = symaddr<float>(g_r);
    float* xpart  = symaddr<float>(g_xpart);
    float* aval   = symaddr<float>(g_Aval);
    __nv_bfloat16* xz    = symaddr<__nv_bfloat16>(g_xz);
    __nv_bfloat16* xhi   = symaddr<__nv_bfloat16>(g_xhi);
    __nv_bfloat16* wihi  = symaddr<__nv_bfloat16>(g_wihi);
    __nv_bfloat16* wohi  = symaddr<__nv_bfloat16>(g_wohi);
    __nv_bfloat16* fwhi  = symaddr<__nv_bfloat16>(g_fwhi);
    __nv_bfloat16* xpwhi = symaddr<__nv_bfloat16>(g_xpwhi);
    __nv_bfloat16* xpwlo = symaddr<__nv_bfloat16>(g_xpwlo);
    __nv_bfloat16* xihi  = symaddr<__nv_bfloat16>(g_xihi);
    __nv_bfloat16* yhi   = symaddr<__nv_bfloat16>(g_yhi);
    __nv_bfloat16* fuhi  = symaddr<__nv_bfloat16>(g_fuhi);

    const size_t XI_D = (size_t)MROWS * DINNER;
    const size_t XD_D = (size_t)MROWS * 64;

    // 0) fused prep: bf16 conversions + A' = -exp(A_log)*log2e
    PrepJobs J;
    const int nX  = MROWS * DMODEL / 4;
    const int nWI = WI_SZ / 4, nWO = WO_SZ / 4, nFW = FW_SZ / 4, nXP = XPW_SZ / 4;
    const int nAL = (DINNER * DSTATE) / 4;
    for (int k = 0; k < 10; k++) { J.lo[k] = nullptr; J.fo[k] = nullptr; }
    J.src[0] = (const float4*)x;        J.hi[0] = (ushort4*)xhi;
    J.src[1] = (const float4*)f_in_w;   J.hi[1] = (ushort4*)wihi;
    J.src[2] = (const float4*)b_in_w;   J.hi[2] = (ushort4*)(wihi + WI_SZ);
    J.src[3] = (const float4*)f_out_w;  J.hi[3] = (ushort4*)wohi;
    J.src[4] = (const float4*)b_out_w;  J.hi[4] = (ushort4*)(wohi + WO_SZ);
    J.src[5] = (const float4*)fusion_w; J.hi[5] = (ushort4*)fwhi;
    J.src[6] = (const float4*)f_xproj;  J.hi[6] = (ushort4*)xpwhi;            J.lo[6] = (ushort4*)xpwlo;
    J.src[7] = (const float4*)b_xproj;  J.hi[7] = (ushort4*)(xpwhi + XPW_SZ); J.lo[7] = (ushort4*)(xpwlo + XPW_SZ);
    J.src[8] = (const float4*)f_A_log;  J.hi[8] = nullptr; J.fo[8] = (float4*)aval;
    J.src[9] = (const float4*)b_A_log;  J.hi[9] = nullptr; J.fo[9] = (float4*)(aval + DINNER * DSTATE);
    int e = 0;
    e += nX;  J.end4[0] = e;
    e += nWI; J.end4[1] = e;
    e += nWI; J.end4[2] = e;
    e += nWO; J.end4[3] = e;
    e += nWO; J.end4[4] = e;
    e += nFW; J.end4[5] = e;
    e += nXP; J.end4[6] = e;
    e += nXP; J.end4[7] = e;
    e += nAL; J.end4[8] = e;
    e += nAL; J.end4[9] = e;
    prep_all_kernel<<<(e + 255) / 256, 256>>>(J);

    // 1) in_proj (HMMA 1-pass, double-buffered): xz[dir] = x(_flip) @ in_w^T
    mma_gemm<true, false, 1, false, 1><<<dim3(32, 16, 2), 128>>>(
        xhi, wihi, nullptr, wihi + WI_SZ, nullptr,
        nullptr, xz, 0, (size_t)MROWS * 2 * DINNER, 0,
        DMODEL, DMODEL, DMODEL, 2 * DINNER);

    // 2) causal depthwise conv + SiLU (preloaded window) -> xihi
    conv_silu_kernel<<<dim3(128, 4), 256>>>(f_conv_w, f_conv_b, b_conv_w, b_conv_b);

    // 3) xproj (HMMA 2-pass B-split, split-K4): x_dbl = xi @ xproj_w^T
    mma_gemm<false, false, 0, true, XKS><<<dim3(1, 16, 2 * XKS), 128>>>(
        xihi, xpwhi, xpwlo, xpwhi + XPW_SZ, xpwlo + XPW_SZ,
        xpart, nullptr, XI_D, (size_t)XKS * MROWS * 64, (size_t)MROWS * 64,
        DINNER, DINNER, DINNER, 64);
    xdbl_reduce_kernel<<<(2 * MROWS * 64) / 256, 256>>>();

    // 4) dtproj (SIMT): delta = softplus(dt @ dt_w^T + dt_b)
    gemm_nt<64, 64, 16, 4, 4, true>
        <<<dim3(16, 32, 2), 256>>>(xdbl, f_dt_w, b_dt_w, delta, f_dt_b, b_dt_b,
                                   XD_D, XI_D, MROWS, DINNER, DTRANK, 64, DTRANK, DINNER);

    // 5) chunked selective scan (+ fused gating, emits yhi)
    scanA_kernel<<<dim3(32, CH, 4), 128>>>();
    scanB_kernel<<<128, 128>>>();
    scanC_kernel<<<dim3(32, CH, 4), 128>>>(f_D, b_D);

    // 6) out_proj (HMMA 1-pass, double-buffered): fusein = y @ out_w^T
    mma_gemm<false, true, 1, false, 1><<<dim3(8, 16, 2), 128>>>(
        yhi, wohi, nullptr, wohi + WO_SZ, nullptr,
        nullptr, fuhi, XI_D, (size_t)DMODEL, 0,
        DINNER, DINNER, DINNER, 2 * DMODEL);

    // 7) fusion (HMMA 1-pass, double-buffered): r = fused @ fusion_w^T
    mma_gemm<false, false, 0, false, 1><<<dim3(8, 16, 1), 128>>>(
        fuhi, fwhi, nullptr, fwhi, nullptr,
        rbuf, nullptr, 0, 0, 0,
        2 * DMODEL, 2 * DMODEL, 2 * DMODEL, DMODEL);

    // 8) residual + bias + layernorm -> d_out
    ln_kernel<<<MROWS, 256>>>(x, fusion_b, ln_g, ln_b, out);

    (void)n_in; (void)out_size;
}